// round 1
// baseline (speedup 1.0000x reference)
#include <cuda_runtime.h>
#include <math.h>

// ---------------------------------------------------------------------------
// Problem constants
// ---------------------------------------------------------------------------
#define LSEQ   8192
#define KNODES 4096
#define ESZ    32
#define DSZ    64
#define NBINS  33          // D/2+1 rFFT bins
#define PI2F   6.283185307179586f

// ---------------------------------------------------------------------------
// Device scratch (no allocations allowed)
// ---------------------------------------------------------------------------
__device__ __align__(16) float2 g_coef[12 * NBINS];   // [p*4+c][k] = tanh(sign)*softmax(hash) rfft / L
__device__ __align__(16) float2 g_T3[NBINS];          // final sketch spectrum
__device__ __align__(16) float  g_present[KNODES];
__device__ __align__(16) float  g_h1[KNODES * ESZ];
__device__ __align__(16) float  g_h2[KNODES * ESZ];
__device__ __align__(16) float  g_qkv[KNODES * 96];
__device__ __align__(16) float  g_accum[ESZ];         // present-masked sum of attention outputs (pre out-proj)
__device__ float g_Np;

// ---------------------------------------------------------------------------
// complex helpers
// ---------------------------------------------------------------------------
__device__ __forceinline__ float2 cadd(float2 a, float2 b) { return make_float2(a.x + b.x, a.y + b.y); }
__device__ __forceinline__ float2 cmul(float2 a, float2 b) {
    return make_float2(a.x * b.x - a.y * b.y, a.x * b.y + a.y * b.x);
}
__device__ __forceinline__ float2 cfma(float2 a, float2 b, float2 c) {  // a*b + c
    c.x = fmaf(a.x, b.x, fmaf(-a.y, b.y, c.x));
    c.y = fmaf(a.x, b.y, fmaf(a.y, b.x, c.y));
    return c;
}

// ---------------------------------------------------------------------------
// K0: zero scratch (runs every graph replay)
// ---------------------------------------------------------------------------
__global__ void zero_kernel() {
    int i = blockIdx.x * blockDim.x + threadIdx.x;
    if (i < KNODES) g_present[i] = 0.f;
    if (i < ESZ)    g_accum[i]   = 0.f;
    if (i == 0)     g_Np         = 0.f;
}

// ---------------------------------------------------------------------------
// K1: softmax(hash) rows, tanh(sign), direct rDFT -> per-char per-level complex coefs
// ---------------------------------------------------------------------------
__global__ void prep_kernel(const float* __restrict__ hash_logits,
                            const float* __restrict__ sign_logits) {
    __shared__ float hs[12][DSZ];
    __shared__ float sg[12];
    int tid = threadIdx.x;
    if (tid < 12) {
        const float* row = hash_logits + tid * DSZ;
        float mx = row[0];
        for (int d = 1; d < DSZ; d++) mx = fmaxf(mx, row[d]);
        float s = 0.f;
        for (int d = 0; d < DSZ; d++) { float e = expf(row[d] - mx); hs[tid][d] = e; s += e; }
        float inv = 1.f / s;
        for (int d = 0; d < DSZ; d++) hs[tid][d] *= inv;
        sg[tid] = tanhf(sign_logits[tid]);
    }
    __syncthreads();
    for (int idx = tid; idx < 12 * NBINS; idx += blockDim.x) {
        int r = idx / NBINS, k = idx % NBINS;
        float re = 0.f, im = 0.f;
        for (int d = 0; d < DSZ; d++) {
            float ang = -PI2F * (float)(k * d) / (float)DSZ;
            float sn, cs; sincosf(ang, &sn, &cs);
            re = fmaf(hs[r][d], cs, re);
            im = fmaf(hs[r][d], sn, im);
        }
        float f = sg[r] * (1.f / (float)LSEQ);
        g_coef[idx] = make_float2(re * f, im * f);
    }
}

// ---------------------------------------------------------------------------
// K2: k-mer presence scatter
// ---------------------------------------------------------------------------
__global__ void scatter_kernel(const int* __restrict__ seq) {
    int t = blockIdx.x * blockDim.x + threadIdx.x;
    if (t < LSEQ - 5) {
        int id = ((((seq[t] * 4 + seq[t + 1]) * 4 + seq[t + 2]) * 4 + seq[t + 3]) * 4
                  + seq[t + 4]) * 4 + seq[t + 5];
        g_present[id] = 1.f;
    }
}

// ---------------------------------------------------------------------------
// K3: tensor-sketch scan as parallel triple-nested-sum reduction, per rFFT bin.
// Per bin k (block): T3[k] = sum_{s<t<u} a_s b_t c_u, with a/b/c from 4-entry tables.
// ---------------------------------------------------------------------------
struct Tup { float2 sa, sb, sc, sba, scb, scba; };

__global__ void sketch_kernel(const int* __restrict__ seq) {
    int k = blockIdx.x;
    int tid = threadIdx.x;
    __shared__ float2 cA[4], cB[4], cC[4];
    __shared__ Tup tp[256];
    if (tid < 4) {
        cA[tid] = g_coef[(0 * 4 + tid) * NBINS + k];
        cB[tid] = g_coef[(1 * 4 + tid) * NBINS + k];
        cC[tid] = g_coef[(2 * 4 + tid) * NBINS + k];
    }
    __syncthreads();
    float2 sa = {0,0}, sb = {0,0}, sc = {0,0}, sba = {0,0}, scb = {0,0}, scba = {0,0};
    int t0 = tid * 32;
    #pragma unroll 4
    for (int i = 0; i < 32; i++) {
        int ch = seq[t0 + i];
        float2 a = cA[ch], b = cB[ch], c = cC[ch];
        scba = cfma(c, sba, scba);   // uses old sba (strict <)
        scb  = cfma(c, sb,  scb);
        sba  = cfma(b, sa,  sba);
        sa = cadd(sa, a); sb = cadd(sb, b); sc = cadd(sc, c);
    }
    Tup me; me.sa = sa; me.sb = sb; me.sc = sc; me.sba = sba; me.scb = scb; me.scba = scba;
    tp[tid] = me;
    __syncthreads();
    for (int s = 128; s > 0; s >>= 1) {
        if (tid < s) {
            Tup X = tp[tid], Y = tp[tid + s];   // X = earlier steps, Y = later
            X.scba = cadd(cadd(X.scba, Y.scba), cadd(cmul(X.sa, Y.scb), cmul(X.sba, Y.sc)));
            X.scb  = cadd(cadd(X.scb,  Y.scb),  cmul(X.sb, Y.sc));
            X.sba  = cadd(cadd(X.sba,  Y.sba),  cmul(X.sa, Y.sb));
            X.sa = cadd(X.sa, Y.sa); X.sb = cadd(X.sb, Y.sb); X.sc = cadd(X.sc, Y.sc);
            tp[tid] = X;
        }
        __syncthreads();
    }
    if (tid == 0) g_T3[k] = tp[0].scba;
}

// ---------------------------------------------------------------------------
// K4: h1 = relu(kmer_emb @ gc1_w^T + b); also reduce Np = sum(present)
// ---------------------------------------------------------------------------
__global__ void h1_kernel(const float* __restrict__ emb,
                          const float* __restrict__ w,
                          const float* __restrict__ b) {
    __shared__ float ws[ESZ * ESZ];
    __shared__ float bs[ESZ];
    __shared__ float wsum[4];
    int tid = threadIdx.x;
    for (int idx = tid; idx < ESZ * ESZ; idx += 128) ws[idx] = w[idx];
    if (tid < ESZ) bs[tid] = b[tid];
    __syncthreads();
    int i = blockIdx.x * 128 + tid;
    float xin[ESZ];
    const float4* e4 = (const float4*)(emb + i * ESZ);
    #pragma unroll
    for (int j = 0; j < 8; j++) {
        float4 v = e4[j];
        xin[j*4+0] = v.x; xin[j*4+1] = v.y; xin[j*4+2] = v.z; xin[j*4+3] = v.w;
    }
    #pragma unroll
    for (int e = 0; e < ESZ; e++) {
        float acc = bs[e];
        #pragma unroll
        for (int j = 0; j < ESZ; j++) acc = fmaf(xin[j], ws[e * ESZ + j], acc);
        g_h1[i * ESZ + e] = fmaxf(acc, 0.f);
    }
    float p = g_present[i];
    for (int o = 16; o; o >>= 1) p += __shfl_down_sync(0xffffffffu, p, o);
    if ((tid & 31) == 0) wsum[tid >> 5] = p;
    __syncthreads();
    if (tid == 0) atomicAdd(&g_Np, wsum[0] + wsum[1] + wsum[2] + wsum[3]);
}

// ---------------------------------------------------------------------------
// neighbor aggregation helper: De Bruijn row i has <=4 nonzeros (j//4 == i%1024, j!=i)
// ---------------------------------------------------------------------------
__device__ __forceinline__ void debruijn_agg(int i, const float* __restrict__ src, float* agg) {
    #pragma unroll
    for (int j = 0; j < ESZ; j++) agg[j] = 0.f;
    if (g_present[i] > 0.f) {
        int base = (i & 1023) * 4;
        float rowsum = 0.f;
        #pragma unroll
        for (int r = 0; r < 4; r++) {
            int j = base + r;
            if (j != i && g_present[j] > 0.f) {
                rowsum += 1.f;
                #pragma unroll
                for (int e = 0; e < ESZ; e++) agg[e] += src[j * ESZ + e];
            }
        }
        float norm = 1.f / (rowsum + 1e-6f);
        #pragma unroll
        for (int e = 0; e < ESZ; e++) agg[e] *= norm;
    }
}

// ---------------------------------------------------------------------------
// K5: h2 = relu((nadj@h1) @ gc2_w^T + b)
// ---------------------------------------------------------------------------
__global__ void h2_kernel(const float* __restrict__ w, const float* __restrict__ b) {
    __shared__ float ws[ESZ * ESZ];
    __shared__ float bs[ESZ];
    int tid = threadIdx.x;
    for (int idx = tid; idx < ESZ * ESZ; idx += 128) ws[idx] = w[idx];
    if (tid < ESZ) bs[tid] = b[tid];
    __syncthreads();
    int i = blockIdx.x * 128 + tid;
    float agg[ESZ];
    debruijn_agg(i, g_h1, agg);
    #pragma unroll
    for (int e = 0; e < ESZ; e++) {
        float acc = bs[e];
        #pragma unroll
        for (int j = 0; j < ESZ; j++) acc = fmaf(agg[j], ws[e * ESZ + j], acc);
        g_h2[i * ESZ + e] = fmaxf(acc, 0.f);
    }
}

// ---------------------------------------------------------------------------
// K6: x = nadj@h2 ; qkv = x @ attn_in_w^T + attn_in_b
// ---------------------------------------------------------------------------
__global__ void xqkv_kernel(const float* __restrict__ w, const float* __restrict__ b) {
    __shared__ float ws[96 * ESZ];
    __shared__ float bs[96];
    int tid = threadIdx.x;
    for (int idx = tid; idx < 96 * ESZ; idx += 128) ws[idx] = w[idx];
    if (tid < 96) bs[tid] = b[tid];
    __syncthreads();
    int i = blockIdx.x * 128 + tid;
    float xv[ESZ];
    debruijn_agg(i, g_h2, xv);
    #pragma unroll 4
    for (int o = 0; o < 96; o++) {
        float acc = bs[o];
        #pragma unroll
        for (int j = 0; j < ESZ; j++) acc = fmaf(xv[j], ws[o * ESZ + j], acc);
        g_qkv[i * 96 + o] = acc;
    }
}

// ---------------------------------------------------------------------------
// K7: masked multihead flash attention; never materializes scores or per-query
// outputs. Folds the present-masked sum directly into g_accum (out-proj is
// linear -> applied after the mean in the final kernel).
// grid = (64 query tiles, 4 heads), 256 threads: 64 queries x 4 key-quads.
// ---------------------------------------------------------------------------
__global__ void attn_kernel() {
    __shared__ __align__(16) float ks[256][8];
    __shared__ __align__(16) float vs[256][8];
    __shared__ float ps[256];
    __shared__ float blockacc[8];
    int h = blockIdx.y, qt = blockIdx.x;
    int tid = threadIdx.x;
    int ql = tid >> 2, quad = tid & 3;
    int qi = qt * 64 + ql;
    float qpres = g_present[qi];
    const float scale = 0.35355339059327373f;   // 1/sqrt(8)
    float qv[8];
    #pragma unroll
    for (int d = 0; d < 8; d++) qv[d] = g_qkv[qi * 96 + h * 8 + d] * scale;
    if (tid < 8) blockacc[tid] = 0.f;

    float m = -1e30f, l = 0.f, acc[8];
    #pragma unroll
    for (int d = 0; d < 8; d++) acc[d] = 0.f;

    for (int c0 = 0; c0 < KNODES; c0 += 256) {
        __syncthreads();
        for (int idx = tid; idx < 512; idx += 256) {
            int j = idx >> 1, hv = idx & 1;
            float4 kt = *(const float4*)&g_qkv[(c0 + j) * 96 + 32 + h * 8 + hv * 4];
            float4 vt = *(const float4*)&g_qkv[(c0 + j) * 96 + 64 + h * 8 + hv * 4];
            *(float4*)&ks[j][hv * 4] = kt;
            *(float4*)&vs[j][hv * 4] = vt;
        }
        ps[tid] = g_present[c0 + tid];
        __syncthreads();
        if (qpres > 0.f) {
            #pragma unroll 4
            for (int jj = 0; jj < 64; jj++) {
                int j = jj * 4 + quad;
                if (ps[j] <= 0.f) continue;     // exact: masked keys underflow to 0 in ref
                float s = 0.f;
                #pragma unroll
                for (int d = 0; d < 8; d++) s = fmaf(qv[d], ks[j][d], s);
                if (s <= m) {
                    float wgt = expf(s - m);
                    l += wgt;
                    #pragma unroll
                    for (int d = 0; d < 8; d++) acc[d] = fmaf(wgt, vs[j][d], acc[d]);
                } else {
                    float corr = expf(m - s);
                    l = fmaf(l, corr, 1.f);
                    #pragma unroll
                    for (int d = 0; d < 8; d++) acc[d] = fmaf(acc[d], corr, vs[j][d]);
                    m = s;
                }
            }
        }
    }

    // merge the 4 key-quads of each query (adjacent lanes in-warp)
    #pragma unroll
    for (int o = 1; o < 4; o <<= 1) {
        float mo = __shfl_xor_sync(0xffffffffu, m, o);
        float lo = __shfl_xor_sync(0xffffffffu, l, o);
        float ao[8];
        #pragma unroll
        for (int d = 0; d < 8; d++) ao[d] = __shfl_xor_sync(0xffffffffu, acc[d], o);
        float mn = fmaxf(m, mo);
        float c1 = expf(m - mn), c2 = expf(mo - mn);
        l = l * c1 + lo * c2;
        #pragma unroll
        for (int d = 0; d < 8; d++) acc[d] = acc[d] * c1 + ao[d] * c2;
        m = mn;
    }
    __syncthreads();
    if (quad == 0 && qpres > 0.f && l > 0.f) {
        float invl = 1.f / l;
        #pragma unroll
        for (int d = 0; d < 8; d++) atomicAdd(&blockacc[d], acc[d] * invl);
    }
    __syncthreads();
    if (tid < 8) atomicAdd(&g_accum[h * 8 + tid], blockacc[tid]);
}

// ---------------------------------------------------------------------------
// K8: out-proj on the masked mean, ctx MLP, irfft sketch, fusion MLP, tanh
// ---------------------------------------------------------------------------
__global__ void final_kernel(const float* __restrict__ aow, const float* __restrict__ aob,
                             const float* __restrict__ cw1, const float* __restrict__ cb1,
                             const float* __restrict__ cw2, const float* __restrict__ cb2,
                             const float* __restrict__ fw1, const float* __restrict__ fb1,
                             const float* __restrict__ fw2, const float* __restrict__ fb2,
                             float* __restrict__ out) {
    __shared__ float m[32], gm[32], c1[16], comb[128], f1[128];
    int tid = threadIdx.x;
    float invNp = 1.f / g_Np;
    if (tid < 32) m[tid] = g_accum[tid] * invNp;
    __syncthreads();
    if (tid < 32) {
        float a = aob[tid];
        for (int j = 0; j < 32; j++) a = fmaf(m[j], aow[tid * 32 + j], a);
        gm[tid] = a;
    }
    __syncthreads();
    if (tid < 16) {
        float a = cb1[tid];
        for (int j = 0; j < 32; j++) a = fmaf(gm[j], cw1[tid * 32 + j], a);
        c1[tid] = fmaxf(a, 0.f);
    }
    __syncthreads();
    if (tid < 64) {
        float a = cb2[tid];
        for (int j = 0; j < 16; j++) a = fmaf(c1[j], cw2[tid * 16 + j], a);
        comb[64 + tid] = a;                     // ctx half
        // irfft of T3 (bins 0 and 32 are real by construction)
        float2 T0 = g_T3[0], T32 = g_T3[32];
        float x = T0.x + ((tid & 1) ? -T32.x : T32.x);
        for (int k = 1; k < 32; k++) {
            float2 Tk = g_T3[k];
            float ang = PI2F * (float)(k * tid) / (float)DSZ;
            float sn, cs; sincosf(ang, &sn, &cs);
            x += 2.f * (Tk.x * cs - Tk.y * sn);
        }
        comb[tid] = x * (1.f / (float)DSZ);     // base_sketch half
    }
    __syncthreads();
    if (tid < 128) {
        float a = fb1[tid];
        for (int j = 0; j < 128; j++) a = fmaf(comb[j], fw1[tid * 128 + j], a);
        f1[tid] = fmaxf(a, 0.f);
    }
    __syncthreads();
    if (tid < 64) {
        float a = fb2[tid];
        for (int j = 0; j < 128; j++) a = fmaf(f1[j], fw2[tid * 128 + j], a);
        out[tid] = tanhf(a);
    }
}

// ---------------------------------------------------------------------------
// launch
// ---------------------------------------------------------------------------
extern "C" void kernel_launch(void* const* d_in, const int* in_sizes, int n_in,
                              void* d_out, int out_size) {
    const int*   seq         = (const int*)  d_in[0];
    const float* hash_logits = (const float*)d_in[1];
    const float* sign_logits = (const float*)d_in[2];
    const float* kmer_emb    = (const float*)d_in[3];
    const float* gc1_w       = (const float*)d_in[4];
    const float* gc1_b       = (const float*)d_in[5];
    const float* gc2_w       = (const float*)d_in[6];
    const float* gc2_b       = (const float*)d_in[7];
    const float* attn_in_w   = (const float*)d_in[8];
    const float* attn_in_b   = (const float*)d_in[9];
    const float* attn_out_w  = (const float*)d_in[10];
    const float* attn_out_b  = (const float*)d_in[11];
    const float* ctx_w1      = (const float*)d_in[12];
    const float* ctx_b1      = (const float*)d_in[13];
    const float* ctx_w2      = (const float*)d_in[14];
    const float* ctx_b2      = (const float*)d_in[15];
    const float* fus_w1      = (const float*)d_in[16];
    const float* fus_b1      = (const float*)d_in[17];
    const float* fus_w2      = (const float*)d_in[18];
    const float* fus_b2      = (const float*)d_in[19];
    float* out = (float*)d_out;

    zero_kernel<<<8, 512>>>();
    prep_kernel<<<1, 128>>>(hash_logits, sign_logits);
    scatter_kernel<<<32, 256>>>(seq);
    sketch_kernel<<<NBINS, 256>>>(seq);
    h1_kernel<<<32, 128>>>(kmer_emb, gc1_w, gc1_b);
    h2_kernel<<<32, 128>>>(gc2_w, gc2_b);
    xqkv_kernel<<<32, 128>>>(attn_in_w, attn_in_b);
    attn_kernel<<<dim3(64, 4), 256>>>();
    final_kernel<<<1, 128>>>(attn_out_w, attn_out_b, ctx_w1, ctx_b1, ctx_w2, ctx_b2,
                             fus_w1, fus_b1, fus_w2, fus_b2, out);
}

// round 2
// speedup vs baseline: 1.0293x; 1.0293x over previous
#include <cuda_runtime.h>
#include <math.h>

// ---------------------------------------------------------------------------
// Problem constants
// ---------------------------------------------------------------------------
#define LSEQ   8192
#define KNODES 4096
#define ESZ    32
#define DSZ    64
#define NBINS  33          // D/2+1 rFFT bins
#define PI2F   6.283185307179586f
#define KSPLIT 5

// ---------------------------------------------------------------------------
// Device scratch (no allocations allowed)
// ---------------------------------------------------------------------------
struct Tup { float2 sa, sb, sc, sba, scb, scba; };

__device__ __align__(16) float2 g_coef[12 * NBINS];
__device__ __align__(16) Tup    g_spart[NBINS * 8];      // sketch segment partials
__device__ __align__(16) float  g_present[KNODES];
__device__ __align__(16) float  g_h1[KNODES * ESZ];
__device__ __align__(16) float  g_h2[KNODES * ESZ];
__device__ __align__(16) float  g_qkv[KNODES * 96];
__device__ __align__(16) float  g_Qc[KNODES * 32];       // compacted, pre-scaled
__device__ __align__(16) float  g_Kc[KNODES * 32];
__device__ __align__(16) float  g_Vc[KNODES * 32];
__device__ int   g_M[KNODES * 4];                        // enc(max score) per (q,h)
__device__ float g_L[KNODES * 4];                        // softmax denominators
__device__ __align__(16) float g_ACCA[KNODES * 4 * 8];   // softmax numerators
__device__ __align__(16) float g_accum[ESZ];
__device__ int   g_cnt;
__device__ float g_Np;

// ---------------------------------------------------------------------------
// helpers
// ---------------------------------------------------------------------------
__device__ __forceinline__ float2 cadd(float2 a, float2 b) { return make_float2(a.x + b.x, a.y + b.y); }
__device__ __forceinline__ float2 cmul(float2 a, float2 b) {
    return make_float2(a.x * b.x - a.y * b.y, a.x * b.y + a.y * b.x);
}
__device__ __forceinline__ float2 cfma(float2 a, float2 b, float2 c) {
    c.x = fmaf(a.x, b.x, fmaf(-a.y, b.y, c.x));
    c.y = fmaf(a.x, b.y, fmaf(a.y, b.x, c.y));
    return c;
}
__device__ __forceinline__ Tup tmerge(Tup X, Tup Y) {   // X = earlier segment
    Tup R;
    R.scba = cadd(cadd(X.scba, Y.scba), cadd(cmul(X.sa, Y.scb), cmul(X.sba, Y.sc)));
    R.scb  = cadd(cadd(X.scb,  Y.scb),  cmul(X.sb, Y.sc));
    R.sba  = cadd(cadd(X.sba,  Y.sba),  cmul(X.sa, Y.sb));
    R.sa = cadd(X.sa, Y.sa); R.sb = cadd(X.sb, Y.sb); R.sc = cadd(X.sc, Y.sc);
    return R;
}
__device__ __forceinline__ int   fenc(float f) { int i = __float_as_int(f); return i < 0 ? i ^ 0x7FFFFFFF : i; }
__device__ __forceinline__ float fdec(int i)   { return __int_as_float(i < 0 ? i ^ 0x7FFFFFFF : i); }

// ---------------------------------------------------------------------------
// K0: zero/init scratch (every replay)
// ---------------------------------------------------------------------------
__global__ void zero_kernel() {
    int i = blockIdx.x * blockDim.x + threadIdx.x;
    if (i < KNODES)         g_present[i] = 0.f;
    if (i < KNODES * 4)   { g_M[i] = fenc(-3e38f); g_L[i] = 0.f; }
    if (i < KNODES * 32)    g_ACCA[i] = 0.f;
    if (i == 0)             g_cnt = 0;
}

// ---------------------------------------------------------------------------
// K1: softmax(hash), tanh(sign), direct rDFT -> per-char per-level coefs
// ---------------------------------------------------------------------------
__global__ void prep_kernel(const float* __restrict__ hash_logits,
                            const float* __restrict__ sign_logits) {
    __shared__ float hs[12][DSZ];
    __shared__ float sg[12];
    int tid = threadIdx.x;
    if (tid < 12) {
        const float* row = hash_logits + tid * DSZ;
        float mx = row[0];
        for (int d = 1; d < DSZ; d++) mx = fmaxf(mx, row[d]);
        float s = 0.f;
        for (int d = 0; d < DSZ; d++) { float e = expf(row[d] - mx); hs[tid][d] = e; s += e; }
        float inv = 1.f / s;
        for (int d = 0; d < DSZ; d++) hs[tid][d] *= inv;
        sg[tid] = tanhf(sign_logits[tid]);
    }
    __syncthreads();
    for (int idx = tid; idx < 12 * NBINS; idx += blockDim.x) {
        int r = idx / NBINS, k = idx % NBINS;
        float re = 0.f, im = 0.f;
        for (int d = 0; d < DSZ; d++) {
            float ang = -PI2F * (float)(k * d) / (float)DSZ;
            float sn, cs; sincosf(ang, &sn, &cs);
            re = fmaf(hs[r][d], cs, re);
            im = fmaf(hs[r][d], sn, im);
        }
        float f = sg[r] * (1.f / (float)LSEQ);
        g_coef[idx] = make_float2(re * f, im * f);
    }
}

// ---------------------------------------------------------------------------
// K2: k-mer presence scatter
// ---------------------------------------------------------------------------
__global__ void scatter_kernel(const int* __restrict__ seq) {
    int t = blockIdx.x * blockDim.x + threadIdx.x;
    if (t < LSEQ - 5) {
        int id = ((((seq[t] * 4 + seq[t + 1]) * 4 + seq[t + 2]) * 4 + seq[t + 3]) * 4
                  + seq[t + 4]) * 4 + seq[t + 5];
        g_present[id] = 1.f;
    }
}

// ---------------------------------------------------------------------------
// K3: tensor-sketch triple-sum, segment-parallel: grid (33 bins, 8 segments)
// Each thread handles 4 consecutive steps; block tree-merges 256 tuples.
// ---------------------------------------------------------------------------
__global__ void sketch_kernel(const int* __restrict__ seq) {
    int bin = blockIdx.x, seg = blockIdx.y;
    int tid = threadIdx.x;
    __shared__ float2 cA[4], cB[4], cC[4];
    __shared__ Tup tp[256];
    if (tid < 4) {
        cA[tid] = g_coef[(0 * 4 + tid) * NBINS + bin];
        cB[tid] = g_coef[(1 * 4 + tid) * NBINS + bin];
        cC[tid] = g_coef[(2 * 4 + tid) * NBINS + bin];
    }
    __syncthreads();
    float2 sa = {0,0}, sb = {0,0}, sc = {0,0}, sba = {0,0}, scb = {0,0}, scba = {0,0};
    int t0 = seg * 1024 + tid * 4;
    #pragma unroll
    for (int i = 0; i < 4; i++) {
        int ch = seq[t0 + i];
        float2 a = cA[ch], b = cB[ch], c = cC[ch];
        scba = cfma(c, sba, scba);
        scb  = cfma(c, sb,  scb);
        sba  = cfma(b, sa,  sba);
        sa = cadd(sa, a); sb = cadd(sb, b); sc = cadd(sc, c);
    }
    Tup me; me.sa = sa; me.sb = sb; me.sc = sc; me.sba = sba; me.scb = scb; me.scba = scba;
    tp[tid] = me;
    __syncthreads();
    for (int s = 128; s > 0; s >>= 1) {
        if (tid < s) tp[tid] = tmerge(tp[tid], tp[tid + s]);
        __syncthreads();
    }
    if (tid == 0) g_spart[bin * 8 + seg] = tp[0];
}

// ---------------------------------------------------------------------------
// K4: h1 = relu(kmer_emb @ gc1_w^T + b)
// ---------------------------------------------------------------------------
__global__ void h1_kernel(const float* __restrict__ emb,
                          const float* __restrict__ w,
                          const float* __restrict__ b) {
    __shared__ float ws[ESZ * ESZ];
    __shared__ float bs[ESZ];
    int tid = threadIdx.x;
    for (int idx = tid; idx < ESZ * ESZ; idx += 128) ws[idx] = w[idx];
    if (tid < ESZ) bs[tid] = b[tid];
    __syncthreads();
    int i = blockIdx.x * 128 + tid;
    float xin[ESZ];
    const float4* e4 = (const float4*)(emb + i * ESZ);
    #pragma unroll
    for (int j = 0; j < 8; j++) {
        float4 v = e4[j];
        xin[j*4+0] = v.x; xin[j*4+1] = v.y; xin[j*4+2] = v.z; xin[j*4+3] = v.w;
    }
    #pragma unroll
    for (int e = 0; e < ESZ; e++) {
        float acc = bs[e];
        #pragma unroll
        for (int j = 0; j < ESZ; j++) acc = fmaf(xin[j], ws[e * ESZ + j], acc);
        g_h1[i * ESZ + e] = fmaxf(acc, 0.f);
    }
}

// ---------------------------------------------------------------------------
// De Bruijn row i: <=4 nonzeros at j in [4*(i%1024), 4*(i%1024)+3], j != i
// ---------------------------------------------------------------------------
__device__ __forceinline__ void debruijn_agg(int i, const float* __restrict__ src, float* agg) {
    #pragma unroll
    for (int j = 0; j < ESZ; j++) agg[j] = 0.f;
    if (g_present[i] > 0.f) {
        int base = (i & 1023) * 4;
        float rowsum = 0.f;
        #pragma unroll
        for (int r = 0; r < 4; r++) {
            int j = base + r;
            if (j != i && g_present[j] > 0.f) {
                rowsum += 1.f;
                #pragma unroll
                for (int e = 0; e < ESZ; e++) agg[e] += src[j * ESZ + e];
            }
        }
        float norm = 1.f / (rowsum + 1e-6f);
        #pragma unroll
        for (int e = 0; e < ESZ; e++) agg[e] *= norm;
    }
}

// ---------------------------------------------------------------------------
// K5: h2 = relu((nadj@h1) @ gc2_w^T + b)
// ---------------------------------------------------------------------------
__global__ void h2_kernel(const float* __restrict__ w, const float* __restrict__ b) {
    __shared__ float ws[ESZ * ESZ];
    __shared__ float bs[ESZ];
    int tid = threadIdx.x;
    for (int idx = tid; idx < ESZ * ESZ; idx += 128) ws[idx] = w[idx];
    if (tid < ESZ) bs[tid] = b[tid];
    __syncthreads();
    int i = blockIdx.x * 128 + tid;
    float agg[ESZ];
    debruijn_agg(i, g_h1, agg);
    #pragma unroll
    for (int e = 0; e < ESZ; e++) {
        float acc = bs[e];
        #pragma unroll
        for (int j = 0; j < ESZ; j++) acc = fmaf(agg[j], ws[e * ESZ + j], acc);
        g_h2[i * ESZ + e] = fmaxf(acc, 0.f);
    }
}

// ---------------------------------------------------------------------------
// K6: x = nadj@h2 ; qkv = x @ attn_in_w^T + attn_in_b
// ---------------------------------------------------------------------------
__global__ void xqkv_kernel(const float* __restrict__ w, const float* __restrict__ b) {
    __shared__ float ws[96 * ESZ];
    __shared__ float bs[96];
    int tid = threadIdx.x;
    for (int idx = tid; idx < 96 * ESZ; idx += 128) ws[idx] = w[idx];
    if (tid < 96) bs[tid] = b[tid];
    __syncthreads();
    int i = blockIdx.x * 128 + tid;
    float xv[ESZ];
    debruijn_agg(i, g_h2, xv);
    #pragma unroll 4
    for (int o = 0; o < 96; o++) {
        float acc = bs[o];
        #pragma unroll
        for (int j = 0; j < ESZ; j++) acc = fmaf(xv[j], ws[o * ESZ + j], acc);
        g_qkv[i * 96 + o] = acc;
    }
}

// ---------------------------------------------------------------------------
// K7: compact present nodes (order irrelevant: downstream is set-sum)
// ---------------------------------------------------------------------------
__global__ void compact_kernel() {
    int i = blockIdx.x * blockDim.x + threadIdx.x;
    if (i >= KNODES) return;
    if (g_present[i] > 0.f) {
        int p = atomicAdd(&g_cnt, 1);
        const float scale = 0.35355339059327373f;  // 1/sqrt(8)
        const float4* src = (const float4*)&g_qkv[i * 96];
        float4* q4 = (float4*)&g_Qc[p * 32];
        float4* k4 = (float4*)&g_Kc[p * 32];
        float4* v4 = (float4*)&g_Vc[p * 32];
        #pragma unroll
        for (int j = 0; j < 8; j++) {
            float4 q = src[j];
            q.x *= scale; q.y *= scale; q.z *= scale; q.w *= scale;
            q4[j] = q;
            k4[j] = src[8 + j];
            v4[j] = src[16 + j];
        }
    }
}

// ---------------------------------------------------------------------------
// K8: per-(q,h) score max. grid (8 qtiles, 4 heads, KSPLIT), 256 thr, 2 q/thr.
// Branchless inner loop: independent FMNMX chains, no data-dependent control.
// ---------------------------------------------------------------------------
__global__ void maxk_kernel() {
    __shared__ __align__(16) float4 ks4[256];   // 128 keys x 8 floats
    int h = blockIdx.y, z = blockIdx.z;
    int tid = threadIdx.x;
    int np = g_cnt;
    int q0 = blockIdx.x * 512 + tid * 2;
    bool v0 = q0 < np, v1 = q0 + 1 < np;
    float qa[8], qb[8];
    #pragma unroll
    for (int d = 0; d < 8; d++) { qa[d] = 0.f; qb[d] = 0.f; }
    if (v0) { float4 x = *(const float4*)&g_Qc[q0*32 + h*8];     qa[0]=x.x;qa[1]=x.y;qa[2]=x.z;qa[3]=x.w;
              x = *(const float4*)&g_Qc[q0*32 + h*8 + 4];        qa[4]=x.x;qa[5]=x.y;qa[6]=x.z;qa[7]=x.w; }
    if (v1) { float4 x = *(const float4*)&g_Qc[(q0+1)*32 + h*8]; qb[0]=x.x;qb[1]=x.y;qb[2]=x.z;qb[3]=x.w;
              x = *(const float4*)&g_Qc[(q0+1)*32 + h*8 + 4];    qb[4]=x.x;qb[5]=x.y;qb[6]=x.z;qb[7]=x.w; }
    int kper = (np + KSPLIT - 1) / KSPLIT;
    int kbeg = z * kper, kend = min(np, kbeg + kper);
    float m0 = -3e38f, m1 = -3e38f;
    for (int kt = kbeg; kt < kend; kt += 128) {
        int jn = min(128, kend - kt);
        __syncthreads();
        {
            int j = tid >> 1, half = tid & 1;
            if (j < jn) ks4[tid] = *(const float4*)&g_Kc[(kt + j) * 32 + h * 8 + half * 4];
        }
        __syncthreads();
        #pragma unroll 4
        for (int j = 0; j < jn; j++) {
            float4 k0 = ks4[j * 2], k1 = ks4[j * 2 + 1];
            float s0 = qa[0]*k0.x + qa[1]*k0.y + qa[2]*k0.z + qa[3]*k0.w
                     + qa[4]*k1.x + qa[5]*k1.y + qa[6]*k1.z + qa[7]*k1.w;
            float s1 = qb[0]*k0.x + qb[1]*k0.y + qb[2]*k0.z + qb[3]*k0.w
                     + qb[4]*k1.x + qb[5]*k1.y + qb[6]*k1.z + qb[7]*k1.w;
            m0 = fmaxf(m0, s0);
            m1 = fmaxf(m1, s1);
        }
    }
    if (v0) atomicMax(&g_M[q0 * 4 + h], fenc(m0));
    if (v1) atomicMax(&g_M[(q0 + 1) * 4 + h], fenc(m1));
}

// ---------------------------------------------------------------------------
// K9: sum exp(s-M) and exp-weighted V, atomically merged across key slices.
// Exact vs reference: M is the true global row max, so merging is plain adds.
// ---------------------------------------------------------------------------
__global__ void sumexp_kernel() {
    __shared__ __align__(16) float4 ks4[256];
    __shared__ __align__(16) float4 vs4[256];
    int h = blockIdx.y, z = blockIdx.z;
    int tid = threadIdx.x;
    int np = g_cnt;
    int q0 = blockIdx.x * 512 + tid * 2;
    bool v0 = q0 < np, v1 = q0 + 1 < np;
    float qa[8], qb[8];
    #pragma unroll
    for (int d = 0; d < 8; d++) { qa[d] = 0.f; qb[d] = 0.f; }
    float m0 = 0.f, m1 = 0.f;
    if (v0) { float4 x = *(const float4*)&g_Qc[q0*32 + h*8];     qa[0]=x.x;qa[1]=x.y;qa[2]=x.z;qa[3]=x.w;
              x = *(const float4*)&g_Qc[q0*32 + h*8 + 4];        qa[4]=x.x;qa[5]=x.y;qa[6]=x.z;qa[7]=x.w;
              m0 = fdec(g_M[q0 * 4 + h]); }
    if (v1) { float4 x = *(const float4*)&g_Qc[(q0+1)*32 + h*8]; qb[0]=x.x;qb[1]=x.y;qb[2]=x.z;qb[3]=x.w;
              x = *(const float4*)&g_Qc[(q0+1)*32 + h*8 + 4];    qb[4]=x.x;qb[5]=x.y;qb[6]=x.z;qb[7]=x.w;
              m1 = fdec(g_M[(q0 + 1) * 4 + h]); }
    int kper = (np + KSPLIT - 1) / KSPLIT;
    int kbeg = z * kper, kend = min(np, kbeg + kper);
    float l0 = 0.f, l1 = 0.f;
    float acc0[8], acc1[8];
    #pragma unroll
    for (int d = 0; d < 8; d++) { acc0[d] = 0.f; acc1[d] = 0.f; }
    for (int kt = kbeg; kt < kend; kt += 128) {
        int jn = min(128, kend - kt);
        __syncthreads();
        for (int idx = tid; idx < 512; idx += 256) {
            int j = idx >> 2, c = idx & 3;
            if (j < jn) {
                int row = (kt + j) * 32 + h * 8 + (c & 1) * 4;
                if (c < 2) ks4[j * 2 + c]       = *(const float4*)&g_Kc[row];
                else       vs4[j * 2 + (c - 2)] = *(const float4*)&g_Vc[row];
            }
        }
        __syncthreads();
        #pragma unroll 2
        for (int j = 0; j < jn; j++) {
            float4 k0 = ks4[j * 2], k1 = ks4[j * 2 + 1];
            float s0 = qa[0]*k0.x + qa[1]*k0.y + qa[2]*k0.z + qa[3]*k0.w
                     + qa[4]*k1.x + qa[5]*k1.y + qa[6]*k1.z + qa[7]*k1.w;
            float s1 = qb[0]*k0.x + qb[1]*k0.y + qb[2]*k0.z + qb[3]*k0.w
                     + qb[4]*k1.x + qb[5]*k1.y + qb[6]*k1.z + qb[7]*k1.w;
            float w0 = __expf(s0 - m0);
            float w1 = __expf(s1 - m1);
            l0 += w0; l1 += w1;
            float4 va = vs4[j * 2], vb = vs4[j * 2 + 1];
            acc0[0] = fmaf(w0, va.x, acc0[0]); acc0[1] = fmaf(w0, va.y, acc0[1]);
            acc0[2] = fmaf(w0, va.z, acc0[2]); acc0[3] = fmaf(w0, va.w, acc0[3]);
            acc0[4] = fmaf(w0, vb.x, acc0[4]); acc0[5] = fmaf(w0, vb.y, acc0[5]);
            acc0[6] = fmaf(w0, vb.z, acc0[6]); acc0[7] = fmaf(w0, vb.w, acc0[7]);
            acc1[0] = fmaf(w1, va.x, acc1[0]); acc1[1] = fmaf(w1, va.y, acc1[1]);
            acc1[2] = fmaf(w1, va.z, acc1[2]); acc1[3] = fmaf(w1, va.w, acc1[3]);
            acc1[4] = fmaf(w1, vb.x, acc1[4]); acc1[5] = fmaf(w1, vb.y, acc1[5]);
            acc1[6] = fmaf(w1, vb.z, acc1[6]); acc1[7] = fmaf(w1, vb.w, acc1[7]);
        }
    }
    if (v0) {
        atomicAdd(&g_L[q0 * 4 + h], l0);
        #pragma unroll
        for (int d = 0; d < 8; d++) atomicAdd(&g_ACCA[(q0 * 4 + h) * 8 + d], acc0[d]);
    }
    if (v1) {
        atomicAdd(&g_L[(q0 + 1) * 4 + h], l1);
        #pragma unroll
        for (int d = 0; d < 8; d++) atomicAdd(&g_ACCA[((q0 + 1) * 4 + h) * 8 + d], acc1[d]);
    }
}

// ---------------------------------------------------------------------------
// K10: sum over present queries of (ACC/L) -> g_accum[32]; set g_Np
// ---------------------------------------------------------------------------
__global__ void mean_kernel() {
    __shared__ float sw[8][32];
    int tid = threadIdx.x;
    int np = g_cnt;
    float vec[32];
    #pragma unroll
    for (int d = 0; d < 32; d++) vec[d] = 0.f;
    for (int q = tid; q < np; q += 256) {
        #pragma unroll
        for (int h = 0; h < 4; h++) {
            float invl = 1.f / g_L[q * 4 + h];
            #pragma unroll
            for (int d = 0; d < 8; d++)
                vec[h * 8 + d] = fmaf(g_ACCA[(q * 4 + h) * 8 + d], invl, vec[h * 8 + d]);
        }
    }
    int lane = tid & 31, w = tid >> 5;
    #pragma unroll
    for (int d = 0; d < 32; d++) {
        float r = vec[d];
        for (int o = 16; o; o >>= 1) r += __shfl_xor_sync(0xffffffffu, r, o);
        if (lane == 0) sw[w][d] = r;
    }
    __syncthreads();
    if (tid < 32) {
        float s = 0.f;
        #pragma unroll
        for (int ww = 0; ww < 8; ww++) s += sw[ww][tid];
        g_accum[tid] = s;
    }
    if (tid == 0) g_Np = (float)np;
}

// ---------------------------------------------------------------------------
// K11: sketch segment merge + out-proj + ctx MLP + irfft + fusion MLP + tanh
// ---------------------------------------------------------------------------
__global__ void final_kernel(const float* __restrict__ aow, const float* __restrict__ aob,
                             const float* __restrict__ cw1, const float* __restrict__ cb1,
                             const float* __restrict__ cw2, const float* __restrict__ cb2,
                             const float* __restrict__ fw1, const float* __restrict__ fb1,
                             const float* __restrict__ fw2, const float* __restrict__ fb2,
                             float* __restrict__ out) {
    __shared__ float m[32], gm[32], c1[16], comb[128], f1[128];
    __shared__ float2 sT3[NBINS];
    int tid = threadIdx.x;
    if (tid < NBINS) {                      // ordered merge of 8 sketch segments
        Tup acc = g_spart[tid * 8];
        #pragma unroll
        for (int s = 1; s < 8; s++) acc = tmerge(acc, g_spart[tid * 8 + s]);
        sT3[tid] = acc.scba;
    }
    float invNp = 1.f / g_Np;
    if (tid < 32) m[tid] = g_accum[tid] * invNp;
    __syncthreads();
    if (tid < 32) {
        float a = aob[tid];
        for (int j = 0; j < 32; j++) a = fmaf(m[j], aow[tid * 32 + j], a);
        gm[tid] = a;
    }
    __syncthreads();
    if (tid < 16) {
        float a = cb1[tid];
        for (int j = 0; j < 32; j++) a = fmaf(gm[j], cw1[tid * 32 + j], a);
        c1[tid] = fmaxf(a, 0.f);
    }
    __syncthreads();
    if (tid < 64) {
        float a = cb2[tid];
        for (int j = 0; j < 16; j++) a = fmaf(c1[j], cw2[tid * 16 + j], a);
        comb[64 + tid] = a;
        float2 T0 = sT3[0], T32 = sT3[32];
        float x = T0.x + ((tid & 1) ? -T32.x : T32.x);
        for (int k = 1; k < 32; k++) {
            float2 Tk = sT3[k];
            float ang = PI2F * (float)(k * tid) / (float)DSZ;
            float sn, cs; sincosf(ang, &sn, &cs);
            x += 2.f * (Tk.x * cs - Tk.y * sn);
        }
        comb[tid] = x * (1.f / (float)DSZ);
    }
    __syncthreads();
    if (tid < 128) {
        float a = fb1[tid];
        for (int j = 0; j < 128; j++) a = fmaf(comb[j], fw1[tid * 128 + j], a);
        f1[tid] = fmaxf(a, 0.f);
    }
    __syncthreads();
    if (tid < 64) {
        float a = fb2[tid];
        for (int j = 0; j < 128; j++) a = fmaf(f1[j], fw2[tid * 128 + j], a);
        out[tid] = tanhf(a);
    }
}

// ---------------------------------------------------------------------------
// launch
// ---------------------------------------------------------------------------
extern "C" void kernel_launch(void* const* d_in, const int* in_sizes, int n_in,
                              void* d_out, int out_size) {
    const int*   seq         = (const int*)  d_in[0];
    const float* hash_logits = (const float*)d_in[1];
    const float* sign_logits = (const float*)d_in[2];
    const float* kmer_emb    = (const float*)d_in[3];
    const float* gc1_w       = (const float*)d_in[4];
    const float* gc1_b       = (const float*)d_in[5];
    const float* gc2_w       = (const float*)d_in[6];
    const float* gc2_b       = (const float*)d_in[7];
    const float* attn_in_w   = (const float*)d_in[8];
    const float* attn_in_b   = (const float*)d_in[9];
    const float* attn_out_w  = (const float*)d_in[10];
    const float* attn_out_b  = (const float*)d_in[11];
    const float* ctx_w1      = (const float*)d_in[12];
    const float* ctx_b1      = (const float*)d_in[13];
    const float* ctx_w2      = (const float*)d_in[14];
    const float* ctx_b2      = (const float*)d_in[15];
    const float* fus_w1      = (const float*)d_in[16];
    const float* fus_b1      = (const float*)d_in[17];
    const float* fus_w2      = (const float*)d_in[18];
    const float* fus_b2      = (const float*)d_in[19];
    float* out = (float*)d_out;

    zero_kernel<<<512, 256>>>();
    prep_kernel<<<1, 128>>>(hash_logits, sign_logits);
    scatter_kernel<<<32, 256>>>(seq);
    sketch_kernel<<<dim3(NBINS, 8), 256>>>(seq);
    h1_kernel<<<32, 128>>>(kmer_emb, gc1_w, gc1_b);
    h2_kernel<<<32, 128>>>(gc2_w, gc2_b);
    xqkv_kernel<<<32, 128>>>(attn_in_w, attn_in_b);
    compact_kernel<<<16, 256>>>();
    maxk_kernel<<<dim3(8, 4, KSPLIT), 256>>>();
    sumexp_kernel<<<dim3(8, 4, KSPLIT), 256>>>();
    mean_kernel<<<1, 256>>>();
    final_kernel<<<1, 128>>>(attn_out_w, attn_out_b, ctx_w1, ctx_b1, ctx_w2, ctx_b2,
                             fus_w1, fus_b1, fus_w2, fus_b2, out);
}

// round 3
// speedup vs baseline: 1.7484x; 1.6987x over previous
#include <cuda_runtime.h>
#include <math.h>

// ---------------------------------------------------------------------------
// Problem constants
// ---------------------------------------------------------------------------
#define LSEQ   8192
#define KNODES 4096
#define ESZ    32
#define DSZ    64
#define NBINS  33          // D/2+1 rFFT bins
#define PI2F   6.283185307179586f
#define KSPLIT 18

typedef unsigned long long ull;

// ---------------------------------------------------------------------------
// Device scratch (no allocations allowed)
// ---------------------------------------------------------------------------
struct Tup { float2 sa, sb, sc, sba, scb, scba; };

__device__ __align__(16) Tup    g_spart[NBINS * 8];      // sketch segment partials
__device__ __align__(16) float  g_present[KNODES];
__device__ __align__(16) float  g_h1[KNODES * ESZ];
__device__ __align__(16) float  g_h2[KNODES * ESZ];
__device__ __align__(16) float  g_qkv[KNODES * 96];
__device__ __align__(16) float  g_Qc[KNODES * 32];       // compacted, pre-scaled
__device__ __align__(16) float  g_Kc[KNODES * 32];
__device__ __align__(16) float  g_Vc[KNODES * 32];
__device__ int   g_knmax[4];                             // bits of max ||k_h||^2 per head
__device__ float g_L[KNODES * 4];                        // softmax denominators
__device__ __align__(16) float g_ACCA[KNODES * 4 * 8];   // softmax numerators
__device__ __align__(16) float g_accum[ESZ];
__device__ int   g_cnt;
__device__ float g_Np;

// ---------------------------------------------------------------------------
// helpers
// ---------------------------------------------------------------------------
__device__ __forceinline__ float2 cadd(float2 a, float2 b) { return make_float2(a.x + b.x, a.y + b.y); }
__device__ __forceinline__ float2 cmul(float2 a, float2 b) {
    return make_float2(a.x * b.x - a.y * b.y, a.x * b.y + a.y * b.x);
}
__device__ __forceinline__ float2 cfma(float2 a, float2 b, float2 c) {
    c.x = fmaf(a.x, b.x, fmaf(-a.y, b.y, c.x));
    c.y = fmaf(a.x, b.y, fmaf(a.y, b.x, c.y));
    return c;
}
__device__ __forceinline__ Tup tmerge(Tup X, Tup Y) {   // X = earlier segment
    Tup R;
    R.scba = cadd(cadd(X.scba, Y.scba), cadd(cmul(X.sa, Y.scb), cmul(X.sba, Y.sc)));
    R.scb  = cadd(cadd(X.scb,  Y.scb),  cmul(X.sb, Y.sc));
    R.sba  = cadd(cadd(X.sba,  Y.sba),  cmul(X.sa, Y.sb));
    R.sa = cadd(X.sa, Y.sa); R.sb = cadd(X.sb, Y.sb); R.sc = cadd(X.sc, Y.sc);
    return R;
}
// packed f32x2 (Blackwell)
__device__ __forceinline__ ull pack2(float lo, float hi) {
    ull r; asm("mov.b64 %0, {%1, %2};" : "=l"(r) : "f"(lo), "f"(hi)); return r;
}
__device__ __forceinline__ void unpack2(ull v, float& lo, float& hi) {
    asm("mov.b64 {%0, %1}, %2;" : "=f"(lo), "=f"(hi) : "l"(v));
}
__device__ __forceinline__ ull fma2(ull a, ull b, ull c) {
    ull d; asm("fma.rn.f32x2 %0, %1, %2, %3;" : "=l"(d) : "l"(a), "l"(b), "l"(c)); return d;
}

// ---------------------------------------------------------------------------
// K0: zero/init scratch (every replay)
// ---------------------------------------------------------------------------
__global__ void zero_kernel() {
    int i = blockIdx.x * blockDim.x + threadIdx.x;
    if (i < KNODES)        g_present[i] = 0.f;
    if (i < KNODES * 4)    g_L[i] = 0.f;
    if (i < KNODES * 32)   g_ACCA[i] = 0.f;
    if (i < ESZ)           g_accum[i] = 0.f;
    if (i < 4)             g_knmax[i] = 0;
    if (i == 0)            g_cnt = 0;
}

// ---------------------------------------------------------------------------
// K1: k-mer presence scatter
// ---------------------------------------------------------------------------
__global__ void scatter_kernel(const int* __restrict__ seq) {
    int t = blockIdx.x * blockDim.x + threadIdx.x;
    if (t < LSEQ - 5) {
        int id = ((((seq[t] * 4 + seq[t + 1]) * 4 + seq[t + 2]) * 4 + seq[t + 3]) * 4
                  + seq[t + 4]) * 4 + seq[t + 5];
        g_present[id] = 1.f;
    }
}

// ---------------------------------------------------------------------------
// K2: tensor-sketch triple-sum, segment-parallel: grid (33 bins, 8 segments).
// Each block computes its own bin's 12 complex coefficients (softmax + DFT)
// in-kernel, then does the tuple scan + tree merge.
// ---------------------------------------------------------------------------
__global__ void sketch_kernel(const int* __restrict__ seq,
                              const float* __restrict__ hash_logits,
                              const float* __restrict__ sign_logits) {
    int bin = blockIdx.x, seg = blockIdx.y;
    int tid = threadIdx.x;
    __shared__ float hs[12][DSZ];
    __shared__ float sgs[12];
    __shared__ float2 cA[4], cB[4], cC[4];
    __shared__ Tup tp[256];

    if (tid < 12) {
        const float* row = hash_logits + tid * DSZ;
        float mx = row[0];
        for (int d = 1; d < DSZ; d++) mx = fmaxf(mx, row[d]);
        float s = 0.f;
        for (int d = 0; d < DSZ; d++) { float e = expf(row[d] - mx); hs[tid][d] = e; s += e; }
        float inv = 1.f / s;
        for (int d = 0; d < DSZ; d++) hs[tid][d] *= inv;
        sgs[tid] = tanhf(sign_logits[tid]);
    }
    __syncthreads();
    if (tid < 192) {                       // 12 rows x 16 lanes, 4 DFT terms each
        int row = tid >> 4, l16 = tid & 15;
        float re = 0.f, im = 0.f;
        #pragma unroll
        for (int t = 0; t < 4; t++) {
            int d = l16 * 4 + t;
            float ang = -PI2F * (float)(bin * d) / (float)DSZ;
            float sn, cs; sincosf(ang, &sn, &cs);
            re = fmaf(hs[row][d], cs, re);
            im = fmaf(hs[row][d], sn, im);
        }
        #pragma unroll
        for (int o = 8; o; o >>= 1) {
            re += __shfl_down_sync(0xffffffffu, re, o, 16);
            im += __shfl_down_sync(0xffffffffu, im, o, 16);
        }
        if (l16 == 0) {
            float f = sgs[row] * (1.f / (float)LSEQ);
            float2 v = make_float2(re * f, im * f);
            int p = row >> 2, c = row & 3;
            if (p == 0) cA[c] = v; else if (p == 1) cB[c] = v; else cC[c] = v;
        }
    }
    __syncthreads();

    float2 sa = {0,0}, sb = {0,0}, sc = {0,0}, sba = {0,0}, scb = {0,0}, scba = {0,0};
    int t0 = seg * 1024 + tid * 4;
    #pragma unroll
    for (int i = 0; i < 4; i++) {
        int ch = seq[t0 + i];
        float2 a = cA[ch], b = cB[ch], c = cC[ch];
        scba = cfma(c, sba, scba);
        scb  = cfma(c, sb,  scb);
        sba  = cfma(b, sa,  sba);
        sa = cadd(sa, a); sb = cadd(sb, b); sc = cadd(sc, c);
    }
    Tup me; me.sa = sa; me.sb = sb; me.sc = sc; me.sba = sba; me.scb = scb; me.scba = scba;
    tp[tid] = me;
    __syncthreads();
    for (int s = 128; s > 0; s >>= 1) {
        if (tid < s) tp[tid] = tmerge(tp[tid], tp[tid + s]);
        __syncthreads();
    }
    if (tid == 0) g_spart[bin * 8 + seg] = tp[0];
}

// ---------------------------------------------------------------------------
// K3: h1 = relu(kmer_emb @ gc1_w^T + b)
// ---------------------------------------------------------------------------
__global__ void h1_kernel(const float* __restrict__ emb,
                          const float* __restrict__ w,
                          const float* __restrict__ b) {
    __shared__ float ws[ESZ * ESZ];
    __shared__ float bs[ESZ];
    int tid = threadIdx.x;
    for (int idx = tid; idx < ESZ * ESZ; idx += 128) ws[idx] = w[idx];
    if (tid < ESZ) bs[tid] = b[tid];
    __syncthreads();
    int i = blockIdx.x * 128 + tid;
    float xin[ESZ];
    const float4* e4 = (const float4*)(emb + i * ESZ);
    #pragma unroll
    for (int j = 0; j < 8; j++) {
        float4 v = e4[j];
        xin[j*4+0] = v.x; xin[j*4+1] = v.y; xin[j*4+2] = v.z; xin[j*4+3] = v.w;
    }
    #pragma unroll
    for (int e = 0; e < ESZ; e++) {
        float acc = bs[e];
        #pragma unroll
        for (int j = 0; j < ESZ; j++) acc = fmaf(xin[j], ws[e * ESZ + j], acc);
        g_h1[i * ESZ + e] = fmaxf(acc, 0.f);
    }
}

// ---------------------------------------------------------------------------
// De Bruijn row i: <=4 nonzeros at j in [4*(i%1024), 4*(i%1024)+3], j != i
// ---------------------------------------------------------------------------
__device__ __forceinline__ void debruijn_agg(int i, const float* __restrict__ src, float* agg) {
    #pragma unroll
    for (int j = 0; j < ESZ; j++) agg[j] = 0.f;
    if (g_present[i] > 0.f) {
        int base = (i & 1023) * 4;
        float rowsum = 0.f;
        #pragma unroll
        for (int r = 0; r < 4; r++) {
            int j = base + r;
            if (j != i && g_present[j] > 0.f) {
                rowsum += 1.f;
                #pragma unroll
                for (int e = 0; e < ESZ; e++) agg[e] += src[j * ESZ + e];
            }
        }
        float norm = 1.f / (rowsum + 1e-6f);
        #pragma unroll
        for (int e = 0; e < ESZ; e++) agg[e] *= norm;
    }
}

// ---------------------------------------------------------------------------
// K4: h2 = relu((nadj@h1) @ gc2_w^T + b)
// ---------------------------------------------------------------------------
__global__ void h2_kernel(const float* __restrict__ w, const float* __restrict__ b) {
    __shared__ float ws[ESZ * ESZ];
    __shared__ float bs[ESZ];
    int tid = threadIdx.x;
    for (int idx = tid; idx < ESZ * ESZ; idx += 128) ws[idx] = w[idx];
    if (tid < ESZ) bs[tid] = b[tid];
    __syncthreads();
    int i = blockIdx.x * 128 + tid;
    float agg[ESZ];
    debruijn_agg(i, g_h1, agg);
    #pragma unroll
    for (int e = 0; e < ESZ; e++) {
        float acc = bs[e];
        #pragma unroll
        for (int j = 0; j < ESZ; j++) acc = fmaf(agg[j], ws[e * ESZ + j], acc);
        g_h2[i * ESZ + e] = fmaxf(acc, 0.f);
    }
}

// ---------------------------------------------------------------------------
// K5: x = nadj@h2 ; qkv = x @ attn_in_w^T + attn_in_b
// ---------------------------------------------------------------------------
__global__ void xqkv_kernel(const float* __restrict__ w, const float* __restrict__ b) {
    __shared__ float ws[96 * ESZ];
    __shared__ float bs[96];
    int tid = threadIdx.x;
    for (int idx = tid; idx < 96 * ESZ; idx += 128) ws[idx] = w[idx];
    if (tid < 96) bs[tid] = b[tid];
    __syncthreads();
    int i = blockIdx.x * 128 + tid;
    float xv[ESZ];
    debruijn_agg(i, g_h2, xv);
    #pragma unroll 4
    for (int o = 0; o < 96; o++) {
        float acc = bs[o];
        #pragma unroll
        for (int j = 0; j < ESZ; j++) acc = fmaf(xv[j], ws[o * ESZ + j], acc);
        g_qkv[i * 96 + o] = acc;
    }
}

// ---------------------------------------------------------------------------
// K6: compact present nodes; also max ||k||^2 per head (for the softmax shift
// upper bound). Order irrelevant: downstream is a set-sum.
// ---------------------------------------------------------------------------
__global__ void compact_kernel() {
    int i = blockIdx.x * blockDim.x + threadIdx.x;
    if (i >= KNODES) return;
    if (g_present[i] > 0.f) {
        int p = atomicAdd(&g_cnt, 1);
        const float scale = 0.35355339059327373f;  // 1/sqrt(8)
        const float4* src = (const float4*)&g_qkv[i * 96];
        float4* q4 = (float4*)&g_Qc[p * 32];
        float4* k4 = (float4*)&g_Kc[p * 32];
        float4* v4 = (float4*)&g_Vc[p * 32];
        #pragma unroll
        for (int j = 0; j < 8; j++) {
            float4 q = src[j];
            q.x *= scale; q.y *= scale; q.z *= scale; q.w *= scale;
            q4[j] = q;
            k4[j] = src[8 + j];
            v4[j] = src[16 + j];
        }
        #pragma unroll
        for (int h = 0; h < 4; h++) {
            float4 a = src[8 + 2 * h], b = src[8 + 2 * h + 1];
            float ksq = a.x*a.x + a.y*a.y + a.z*a.z + a.w*a.w
                      + b.x*b.x + b.y*b.y + b.z*b.z + b.w*b.w;
            atomicMax(&g_knmax[h], __float_as_int(ksq));   // ksq >= 0: bit-compare ok
        }
    }
}

// ---------------------------------------------------------------------------
// K7: single-pass softmax numerator/denominator with upper-bound shift.
// m_hat = ||q||*max||k|| >= true max (Cauchy-Schwarz); shift cancels in ACC/L.
// Packed f32x2 FMA for scores and V accumulation. 4 queries/thread.
// grid (4 qtiles, 4 heads, KSPLIT), 256 threads.
// ---------------------------------------------------------------------------
__global__ void __launch_bounds__(256, 2) sumexp_kernel() {
    __shared__ ull ks2[128 * 4];
    __shared__ ull vs2[128 * 4];
    int h = blockIdx.y, z = blockIdx.z;
    int tid = threadIdx.x;
    int np = g_cnt;
    float knorm = sqrtf(__int_as_float(g_knmax[h]));
    int qb = blockIdx.x * 1024 + tid * 4;

    ull qp[4][4], c0[4], acc[4][4];
    float l[4];
    bool val[4];
    #pragma unroll
    for (int u = 0; u < 4; u++) {
        int qi = qb + u;
        val[u] = qi < np;
        float qv[8];
        #pragma unroll
        for (int d = 0; d < 8; d++) qv[d] = 0.f;
        if (val[u]) {
            float4 x0 = *(const float4*)&g_Qc[qi * 32 + h * 8];
            float4 x1 = *(const float4*)&g_Qc[qi * 32 + h * 8 + 4];
            qv[0]=x0.x; qv[1]=x0.y; qv[2]=x0.z; qv[3]=x0.w;
            qv[4]=x1.x; qv[5]=x1.y; qv[6]=x1.z; qv[7]=x1.w;
        }
        float qsq = 0.f;
        #pragma unroll
        for (int d = 0; d < 8; d++) qsq = fmaf(qv[d], qv[d], qsq);
        float mh = fminf(sqrtf(qsq) * knorm, 80.f);
        #pragma unroll
        for (int p = 0; p < 4; p++) qp[u][p] = pack2(qv[2*p], qv[2*p+1]);
        c0[u] = pack2(-mh, 0.f);
        l[u] = 0.f;
        #pragma unroll
        for (int p = 0; p < 4; p++) acc[u][p] = pack2(0.f, 0.f);
    }

    int kper = (np + KSPLIT - 1) / KSPLIT;
    int kbeg = z * kper, kend = min(np, kbeg + kper);
    for (int kt = kbeg; kt < kend; kt += 128) {
        int jn = min(128, kend - kt);
        __syncthreads();
        #pragma unroll
        for (int it = 0; it < 2; it++) {
            int idx = tid + it * 256;
            int j = idx >> 2, p = idx & 3;
            if (j < jn) {
                ks2[idx] = *(const ull*)&g_Kc[(kt + j) * 32 + h * 8 + p * 2];
                vs2[idx] = *(const ull*)&g_Vc[(kt + j) * 32 + h * 8 + p * 2];
            }
        }
        __syncthreads();
        #pragma unroll 2
        for (int j = 0; j < jn; j++) {
            ull k0 = ks2[j*4], k1 = ks2[j*4+1], k2 = ks2[j*4+2], k3 = ks2[j*4+3];
            ull v0 = vs2[j*4], v1 = vs2[j*4+1], v2 = vs2[j*4+2], v3 = vs2[j*4+3];
            #pragma unroll
            for (int u = 0; u < 4; u++) {
                ull sp = fma2(qp[u][0], k0,
                         fma2(qp[u][1], k1,
                         fma2(qp[u][2], k2,
                         fma2(qp[u][3], k3, c0[u]))));
                float lo, hi; unpack2(sp, lo, hi);
                float w = __expf(lo + hi);        // = exp(s - m_hat)
                l[u] += w;
                ull wp = pack2(w, w);
                acc[u][0] = fma2(wp, v0, acc[u][0]);
                acc[u][1] = fma2(wp, v1, acc[u][1]);
                acc[u][2] = fma2(wp, v2, acc[u][2]);
                acc[u][3] = fma2(wp, v3, acc[u][3]);
            }
        }
    }

    #pragma unroll
    for (int u = 0; u < 4; u++) if (val[u]) {
        int qi = qb + u;
        atomicAdd(&g_L[qi * 4 + h], l[u]);
        #pragma unroll
        for (int p = 0; p < 4; p++) {
            float lo, hi; unpack2(acc[u][p], lo, hi);
            atomicAdd(&g_ACCA[(qi * 4 + h) * 8 + p * 2],     lo);
            atomicAdd(&g_ACCA[(qi * 4 + h) * 8 + p * 2 + 1], hi);
        }
    }
}

// ---------------------------------------------------------------------------
// K8: sum over present queries of (ACC/L) -> g_accum[32]; set g_Np. grid 8.
// ---------------------------------------------------------------------------
__global__ void mean_kernel() {
    __shared__ float sw[8][32];
    int tid = threadIdx.x;
    int np = g_cnt;
    float vec[32];
    #pragma unroll
    for (int d = 0; d < 32; d++) vec[d] = 0.f;
    for (int q = blockIdx.x * 256 + tid; q < np; q += 2048) {
        #pragma unroll
        for (int h = 0; h < 4; h++) {
            float invl = 1.f / g_L[q * 4 + h];
            #pragma unroll
            for (int d = 0; d < 8; d++)
                vec[h * 8 + d] = fmaf(g_ACCA[(q * 4 + h) * 8 + d], invl, vec[h * 8 + d]);
        }
    }
    int lane = tid & 31, w = tid >> 5;
    #pragma unroll
    for (int d = 0; d < 32; d++) {
        float r = vec[d];
        for (int o = 16; o; o >>= 1) r += __shfl_xor_sync(0xffffffffu, r, o);
        if (lane == 0) sw[w][d] = r;
    }
    __syncthreads();
    if (tid < 32) {
        float s = 0.f;
        #pragma unroll
        for (int ww = 0; ww < 8; ww++) s += sw[ww][tid];
        atomicAdd(&g_accum[tid], s);
    }
    if (blockIdx.x == 0 && tid == 0) g_Np = (float)np;
}

// ---------------------------------------------------------------------------
// K9: sketch segment merge + out-proj + ctx MLP + irfft + fusion MLP + tanh
// ---------------------------------------------------------------------------
__global__ void final_kernel(const float* __restrict__ aow, const float* __restrict__ aob,
                             const float* __restrict__ cw1, const float* __restrict__ cb1,
                             const float* __restrict__ cw2, const float* __restrict__ cb2,
                             const float* __restrict__ fw1, const float* __restrict__ fb1,
                             const float* __restrict__ fw2, const float* __restrict__ fb2,
                             float* __restrict__ out) {
    __shared__ float m[32], gm[32], c1[16], comb[128], f1[128];
    __shared__ float2 sT3[NBINS];
    int tid = threadIdx.x;
    if (tid < NBINS) {                      // ordered merge of 8 sketch segments
        Tup acc = g_spart[tid * 8];
        #pragma unroll
        for (int s = 1; s < 8; s++) acc = tmerge(acc, g_spart[tid * 8 + s]);
        sT3[tid] = acc.scba;
    }
    float invNp = 1.f / g_Np;
    if (tid < 32) m[tid] = g_accum[tid] * invNp;
    __syncthreads();
    if (tid < 32) {
        float a = aob[tid];
        for (int j = 0; j < 32; j++) a = fmaf(m[j], aow[tid * 32 + j], a);
        gm[tid] = a;
    }
    __syncthreads();
    if (tid < 16) {
        float a = cb1[tid];
        for (int j = 0; j < 32; j++) a = fmaf(gm[j], cw1[tid * 32 + j], a);
        c1[tid] = fmaxf(a, 0.f);
    }
    __syncthreads();
    if (tid < 64) {
        float a = cb2[tid];
        for (int j = 0; j < 16; j++) a = fmaf(c1[j], cw2[tid * 16 + j], a);
        comb[64 + tid] = a;
        float2 T0 = sT3[0], T32 = sT3[32];
        float x = T0.x + ((tid & 1) ? -T32.x : T32.x);
        for (int k = 1; k < 32; k++) {
            float2 Tk = sT3[k];
            float ang = PI2F * (float)(k * tid) / (float)DSZ;
            float sn, cs; sincosf(ang, &sn, &cs);
            x += 2.f * (Tk.x * cs - Tk.y * sn);
        }
        comb[tid] = x * (1.f / (float)DSZ);
    }
    __syncthreads();
    if (tid < 128) {
        float a = fb1[tid];
        for (int j = 0; j < 128; j++) a = fmaf(comb[j], fw1[tid * 128 + j], a);
        f1[tid] = fmaxf(a, 0.f);
    }
    __syncthreads();
    if (tid < 64) {
        float a = fb2[tid];
        for (int j = 0; j < 128; j++) a = fmaf(f1[j], fw2[tid * 128 + j], a);
        out[tid] = tanhf(a);
    }
}

// ---------------------------------------------------------------------------
// launch
// ---------------------------------------------------------------------------
extern "C" void kernel_launch(void* const* d_in, const int* in_sizes, int n_in,
                              void* d_out, int out_size) {
    const int*   seq         = (const int*)  d_in[0];
    const float* hash_logits = (const float*)d_in[1];
    const float* sign_logits = (const float*)d_in[2];
    const float* kmer_emb    = (const float*)d_in[3];
    const float* gc1_w       = (const float*)d_in[4];
    const float* gc1_b       = (const float*)d_in[5];
    const float* gc2_w       = (const float*)d_in[6];
    const float* gc2_b       = (const float*)d_in[7];
    const float* attn_in_w   = (const float*)d_in[8];
    const float* attn_in_b   = (const float*)d_in[9];
    const float* attn_out_w  = (const float*)d_in[10];
    const float* attn_out_b  = (const float*)d_in[11];
    const float* ctx_w1      = (const float*)d_in[12];
    const float* ctx_b1      = (const float*)d_in[13];
    const float* ctx_w2      = (const float*)d_in[14];
    const float* ctx_b2      = (const float*)d_in[15];
    const float* fus_w1      = (const float*)d_in[16];
    const float* fus_b1      = (const float*)d_in[17];
    const float* fus_w2      = (const float*)d_in[18];
    const float* fus_b2      = (const float*)d_in[19];
    float* out = (float*)d_out;

    zero_kernel<<<512, 256>>>();
    scatter_kernel<<<32, 256>>>(seq);
    sketch_kernel<<<dim3(NBINS, 8), 256>>>(seq, hash_logits, sign_logits);
    h1_kernel<<<32, 128>>>(kmer_emb, gc1_w, gc1_b);
    h2_kernel<<<32, 128>>>(gc2_w, gc2_b);
    xqkv_kernel<<<32, 128>>>(attn_in_w, attn_in_b);
    compact_kernel<<<16, 256>>>();
    sumexp_kernel<<<dim3(4, 4, KSPLIT), 256>>>();
    mean_kernel<<<8, 256>>>();
    final_kernel<<<1, 128>>>(attn_out_w, attn_out_b, ctx_w1, ctx_b1, ctx_w2, ctx_b2,
                             fus_w1, fus_b1, fus_w2, fus_b2, out);
}

// round 4
// speedup vs baseline: 1.7578x; 1.0054x over previous
#include <cuda_runtime.h>
#include <math.h>

// ---------------------------------------------------------------------------
// Problem constants
// ---------------------------------------------------------------------------
#define LSEQ   8192
#define KNODES 4096
#define ESZ    32
#define DSZ    64
#define NBINS  33          // D/2+1 rFFT bins
#define PI2F   6.283185307179586f
#define KSPLIT 18

typedef unsigned long long ull;

// ---------------------------------------------------------------------------
// Device scratch (no allocations allowed)
// ---------------------------------------------------------------------------
struct Tup { float2 sa, sb, sc, sba, scb, scba; };

__device__ __align__(16) Tup    g_spart[NBINS * 8];      // sketch segment partials
__device__ __align__(16) float  g_present[KNODES];
__device__ __align__(16) float  g_h1[KNODES * ESZ];
__device__ __align__(16) float  g_h2[KNODES * ESZ];
__device__ __align__(16) float  g_qkv[KNODES * 96];
__device__ __align__(16) float  g_Qc[KNODES * 32];       // compacted, pre-scaled
__device__ __align__(16) float  g_Kc[KNODES * 32];
__device__ __align__(16) float  g_Vc[KNODES * 32];
__device__ int   g_knmax[4];                             // bits of max ||k_h||^2 per head
__device__ float g_L[KNODES * 4];                        // softmax denominators
__device__ __align__(16) float g_ACCA[KNODES * 4 * 8];   // softmax numerators
__device__ __align__(16) float g_accum[ESZ];
__device__ int   g_cnt;
__device__ float g_Np;

// ---------------------------------------------------------------------------
// helpers
// ---------------------------------------------------------------------------
__device__ __forceinline__ float2 cadd(float2 a, float2 b) { return make_float2(a.x + b.x, a.y + b.y); }
__device__ __forceinline__ float2 cmul(float2 a, float2 b) {
    return make_float2(a.x * b.x - a.y * b.y, a.x * b.y + a.y * b.x);
}
__device__ __forceinline__ float2 cfma(float2 a, float2 b, float2 c) {
    c.x = fmaf(a.x, b.x, fmaf(-a.y, b.y, c.x));
    c.y = fmaf(a.x, b.y, fmaf(a.y, b.x, c.y));
    return c;
}
__device__ __forceinline__ Tup tmerge(Tup X, Tup Y) {   // X = earlier segment
    Tup R;
    R.scba = cadd(cadd(X.scba, Y.scba), cadd(cmul(X.sa, Y.scb), cmul(X.sba, Y.sc)));
    R.scb  = cadd(cadd(X.scb,  Y.scb),  cmul(X.sb, Y.sc));
    R.sba  = cadd(cadd(X.sba,  Y.sba),  cmul(X.sa, Y.sb));
    R.sa = cadd(X.sa, Y.sa); R.sb = cadd(X.sb, Y.sb); R.sc = cadd(X.sc, Y.sc);
    return R;
}
// packed f32x2 (Blackwell)
__device__ __forceinline__ ull pack2(float lo, float hi) {
    ull r; asm("mov.b64 %0, {%1, %2};" : "=l"(r) : "f"(lo), "f"(hi)); return r;
}
__device__ __forceinline__ void unpack2(ull v, float& lo, float& hi) {
    asm("mov.b64 {%0, %1}, %2;" : "=f"(lo), "=f"(hi) : "l"(v));
}
__device__ __forceinline__ ull fma2(ull a, ull b, ull c) {
    ull d; asm("fma.rn.f32x2 %0, %1, %2, %3;" : "=l"(d) : "l"(a), "l"(b), "l"(c)); return d;
}

// ---------------------------------------------------------------------------
// K0: zero/init scratch (every replay)
// ---------------------------------------------------------------------------
__global__ void zero_kernel() {
    int i = blockIdx.x * blockDim.x + threadIdx.x;
    if (i < KNODES)        g_present[i] = 0.f;
    if (i < KNODES * 4)    g_L[i] = 0.f;
    if (i < KNODES * 32)   g_ACCA[i] = 0.f;
    if (i < ESZ)           g_accum[i] = 0.f;
    if (i < 4)             g_knmax[i] = 0;
    if (i == 0)            g_cnt = 0;
}

// ---------------------------------------------------------------------------
// K1: k-mer presence scatter
// ---------------------------------------------------------------------------
__global__ void scatter_kernel(const int* __restrict__ seq) {
    int t = blockIdx.x * blockDim.x + threadIdx.x;
    if (t < LSEQ - 5) {
        int id = ((((seq[t] * 4 + seq[t + 1]) * 4 + seq[t + 2]) * 4 + seq[t + 3]) * 4
                  + seq[t + 4]) * 4 + seq[t + 5];
        g_present[id] = 1.f;
    }
}

// ---------------------------------------------------------------------------
// K2: tensor-sketch triple-sum, segment-parallel: grid (33 bins, 8 segments).
// Each block computes its own bin's 12 complex coefficients (softmax + DFT)
// in-kernel, then does the tuple scan + tree merge.
// ---------------------------------------------------------------------------
__global__ void sketch_kernel(const int* __restrict__ seq,
                              const float* __restrict__ hash_logits,
                              const float* __restrict__ sign_logits) {
    int bin = blockIdx.x, seg = blockIdx.y;
    int tid = threadIdx.x;
    __shared__ float hs[12][DSZ];
    __shared__ float sgs[12];
    __shared__ float2 cA[4], cB[4], cC[4];
    __shared__ Tup tp[256];

    if (tid < 12) {
        const float* row = hash_logits + tid * DSZ;
        float mx = row[0];
        for (int d = 1; d < DSZ; d++) mx = fmaxf(mx, row[d]);
        float s = 0.f;
        for (int d = 0; d < DSZ; d++) { float e = expf(row[d] - mx); hs[tid][d] = e; s += e; }
        float inv = 1.f / s;
        for (int d = 0; d < DSZ; d++) hs[tid][d] *= inv;
        sgs[tid] = tanhf(sign_logits[tid]);
    }
    __syncthreads();
    if (tid < 192) {                       // 12 rows x 16 lanes, 4 DFT terms each
        int row = tid >> 4, l16 = tid & 15;
        float re = 0.f, im = 0.f;
        #pragma unroll
        for (int t = 0; t < 4; t++) {
            int d = l16 * 4 + t;
            float ang = -PI2F * (float)(bin * d) / (float)DSZ;
            float sn, cs; sincosf(ang, &sn, &cs);
            re = fmaf(hs[row][d], cs, re);
            im = fmaf(hs[row][d], sn, im);
        }
        #pragma unroll
        for (int o = 8; o; o >>= 1) {
            re += __shfl_down_sync(0xffffffffu, re, o, 16);
            im += __shfl_down_sync(0xffffffffu, im, o, 16);
        }
        if (l16 == 0) {
            float f = sgs[row] * (1.f / (float)LSEQ);
            float2 v = make_float2(re * f, im * f);
            int p = row >> 2, c = row & 3;
            if (p == 0) cA[c] = v; else if (p == 1) cB[c] = v; else cC[c] = v;
        }
    }
    __syncthreads();

    float2 sa = {0,0}, sb = {0,0}, sc = {0,0}, sba = {0,0}, scb = {0,0}, scba = {0,0};
    int t0 = seg * 1024 + tid * 4;
    #pragma unroll
    for (int i = 0; i < 4; i++) {
        int ch = seq[t0 + i];
        float2 a = cA[ch], b = cB[ch], c = cC[ch];
        scba = cfma(c, sba, scba);
        scb  = cfma(c, sb,  scb);
        sba  = cfma(b, sa,  sba);
        sa = cadd(sa, a); sb = cadd(sb, b); sc = cadd(sc, c);
    }
    Tup me; me.sa = sa; me.sb = sb; me.sc = sc; me.sba = sba; me.scb = scb; me.scba = scba;
    tp[tid] = me;
    __syncthreads();
    for (int s = 128; s > 0; s >>= 1) {
        if (tid < s) tp[tid] = tmerge(tp[tid], tp[tid + s]);
        __syncthreads();
    }
    if (tid == 0) g_spart[bin * 8 + seg] = tp[0];
}

// ---------------------------------------------------------------------------
// K3: h1 = relu(kmer_emb @ gc1_w^T + b)
// ---------------------------------------------------------------------------
__global__ void h1_kernel(const float* __restrict__ emb,
                          const float* __restrict__ w,
                          const float* __restrict__ b) {
    __shared__ float ws[ESZ * ESZ];
    __shared__ float bs[ESZ];
    int tid = threadIdx.x;
    for (int idx = tid; idx < ESZ * ESZ; idx += 128) ws[idx] = w[idx];
    if (tid < ESZ) bs[tid] = b[tid];
    __syncthreads();
    int i = blockIdx.x * 128 + tid;
    float xin[ESZ];
    const float4* e4 = (const float4*)(emb + i * ESZ);
    #pragma unroll
    for (int j = 0; j < 8; j++) {
        float4 v = e4[j];
        xin[j*4+0] = v.x; xin[j*4+1] = v.y; xin[j*4+2] = v.z; xin[j*4+3] = v.w;
    }
    #pragma unroll
    for (int e = 0; e < ESZ; e++) {
        float acc = bs[e];
        #pragma unroll
        for (int j = 0; j < ESZ; j++) acc = fmaf(xin[j], ws[e * ESZ + j], acc);
        g_h1[i * ESZ + e] = fmaxf(acc, 0.f);
    }
}

// ---------------------------------------------------------------------------
// De Bruijn row i: <=4 nonzeros at j in [4*(i%1024), 4*(i%1024)+3], j != i
// ---------------------------------------------------------------------------
__device__ __forceinline__ void debruijn_agg(int i, const float* __restrict__ src, float* agg) {
    #pragma unroll
    for (int j = 0; j < ESZ; j++) agg[j] = 0.f;
    if (g_present[i] > 0.f) {
        int base = (i & 1023) * 4;
        float rowsum = 0.f;
        #pragma unroll
        for (int r = 0; r < 4; r++) {
            int j = base + r;
            if (j != i && g_present[j] > 0.f) {
                rowsum += 1.f;
                #pragma unroll
                for (int e = 0; e < ESZ; e++) agg[e] += src[j * ESZ + e];
            }
        }
        float norm = 1.f / (rowsum + 1e-6f);
        #pragma unroll
        for (int e = 0; e < ESZ; e++) agg[e] *= norm;
    }
}

// ---------------------------------------------------------------------------
// K4: h2 = relu((nadj@h1) @ gc2_w^T + b)
// ---------------------------------------------------------------------------
__global__ void h2_kernel(const float* __restrict__ w, const float* __restrict__ b) {
    __shared__ float ws[ESZ * ESZ];
    __shared__ float bs[ESZ];
    int tid = threadIdx.x;
    for (int idx = tid; idx < ESZ * ESZ; idx += 128) ws[idx] = w[idx];
    if (tid < ESZ) bs[tid] = b[tid];
    __syncthreads();
    int i = blockIdx.x * 128 + tid;
    float agg[ESZ];
    debruijn_agg(i, g_h1, agg);
    #pragma unroll
    for (int e = 0; e < ESZ; e++) {
        float acc = bs[e];
        #pragma unroll
        for (int j = 0; j < ESZ; j++) acc = fmaf(agg[j], ws[e * ESZ + j], acc);
        g_h2[i * ESZ + e] = fmaxf(acc, 0.f);
    }
}

// ---------------------------------------------------------------------------
// K5: x = nadj@h2 ; qkv = x @ attn_in_w^T + attn_in_b
// ---------------------------------------------------------------------------
__global__ void xqkv_kernel(const float* __restrict__ w, const float* __restrict__ b) {
    __shared__ float ws[96 * ESZ];
    __shared__ float bs[96];
    int tid = threadIdx.x;
    for (int idx = tid; idx < 96 * ESZ; idx += 128) ws[idx] = w[idx];
    if (tid < 96) bs[tid] = b[tid];
    __syncthreads();
    int i = blockIdx.x * 128 + tid;
    float xv[ESZ];
    debruijn_agg(i, g_h2, xv);
    #pragma unroll 4
    for (int o = 0; o < 96; o++) {
        float acc = bs[o];
        #pragma unroll
        for (int j = 0; j < ESZ; j++) acc = fmaf(xv[j], ws[o * ESZ + j], acc);
        g_qkv[i * 96 + o] = acc;
    }
}

// ---------------------------------------------------------------------------
// K6: compact present nodes; also max ||k||^2 per head (for the softmax shift
// upper bound). Order irrelevant: downstream is a set-sum.
// ---------------------------------------------------------------------------
__global__ void compact_kernel() {
    int i = blockIdx.x * blockDim.x + threadIdx.x;
    if (i >= KNODES) return;
    if (g_present[i] > 0.f) {
        int p = atomicAdd(&g_cnt, 1);
        const float scale = 0.35355339059327373f;  // 1/sqrt(8)
        const float4* src = (const float4*)&g_qkv[i * 96];
        float4* q4 = (float4*)&g_Qc[p * 32];
        float4* k4 = (float4*)&g_Kc[p * 32];
        float4* v4 = (float4*)&g_Vc[p * 32];
        #pragma unroll
        for (int j = 0; j < 8; j++) {
            float4 q = src[j];
            q.x *= scale; q.y *= scale; q.z *= scale; q.w *= scale;
            q4[j] = q;
            k4[j] = src[8 + j];
            v4[j] = src[16 + j];
        }
        #pragma unroll
        for (int h = 0; h < 4; h++) {
            float4 a = src[8 + 2 * h], b = src[8 + 2 * h + 1];
            float ksq = a.x*a.x + a.y*a.y + a.z*a.z + a.w*a.w
                      + b.x*b.x + b.y*b.y + b.z*b.z + b.w*b.w;
            atomicMax(&g_knmax[h], __float_as_int(ksq));   // ksq >= 0: bit-compare ok
        }
    }
}

// ---------------------------------------------------------------------------
// K7: single-pass softmax numerator/denominator with upper-bound shift.
// m_hat = ||q||*max||k|| >= true max (Cauchy-Schwarz); shift cancels in ACC/L.
// Packed f32x2 FMA for scores and V accumulation. 4 queries/thread.
// grid (4 qtiles, 4 heads, KSPLIT), 256 threads.
// ---------------------------------------------------------------------------
__global__ void __launch_bounds__(256, 2) sumexp_kernel() {
    __shared__ ull ks2[128 * 4];
    __shared__ ull vs2[128 * 4];
    int h = blockIdx.y, z = blockIdx.z;
    int tid = threadIdx.x;
    int np = g_cnt;
    float knorm = sqrtf(__int_as_float(g_knmax[h]));
    int qb = blockIdx.x * 1024 + tid * 4;

    ull qp[4][4], c0[4], acc[4][4];
    float l[4];
    bool val[4];
    #pragma unroll
    for (int u = 0; u < 4; u++) {
        int qi = qb + u;
        val[u] = qi < np;
        float qv[8];
        #pragma unroll
        for (int d = 0; d < 8; d++) qv[d] = 0.f;
        if (val[u]) {
            float4 x0 = *(const float4*)&g_Qc[qi * 32 + h * 8];
            float4 x1 = *(const float4*)&g_Qc[qi * 32 + h * 8 + 4];
            qv[0]=x0.x; qv[1]=x0.y; qv[2]=x0.z; qv[3]=x0.w;
            qv[4]=x1.x; qv[5]=x1.y; qv[6]=x1.z; qv[7]=x1.w;
        }
        float qsq = 0.f;
        #pragma unroll
        for (int d = 0; d < 8; d++) qsq = fmaf(qv[d], qv[d], qsq);
        float mh = fminf(sqrtf(qsq) * knorm, 80.f);
        #pragma unroll
        for (int p = 0; p < 4; p++) qp[u][p] = pack2(qv[2*p], qv[2*p+1]);
        c0[u] = pack2(-mh, 0.f);
        l[u] = 0.f;
        #pragma unroll
        for (int p = 0; p < 4; p++) acc[u][p] = pack2(0.f, 0.f);
    }

    int kper = (np + KSPLIT - 1) / KSPLIT;
    int kbeg = z * kper, kend = min(np, kbeg + kper);
    for (int kt = kbeg; kt < kend; kt += 128) {
        int jn = min(128, kend - kt);
        __syncthreads();
        #pragma unroll
        for (int it = 0; it < 2; it++) {
            int idx = tid + it * 256;
            int j = idx >> 2, p = idx & 3;
            if (j < jn) {
                ks2[idx] = *(const ull*)&g_Kc[(kt + j) * 32 + h * 8 + p * 2];
                vs2[idx] = *(const ull*)&g_Vc[(kt + j) * 32 + h * 8 + p * 2];
            }
        }
        __syncthreads();
        #pragma unroll 2
        for (int j = 0; j < jn; j++) {
            ull k0 = ks2[j*4], k1 = ks2[j*4+1], k2 = ks2[j*4+2], k3 = ks2[j*4+3];
            ull v0 = vs2[j*4], v1 = vs2[j*4+1], v2 = vs2[j*4+2], v3 = vs2[j*4+3];
            #pragma unroll
            for (int u = 0; u < 4; u++) {
                ull sp = fma2(qp[u][0], k0,
                         fma2(qp[u][1], k1,
                         fma2(qp[u][2], k2,
                         fma2(qp[u][3], k3, c0[u]))));
                float lo, hi; unpack2(sp, lo, hi);
                float w = __expf(lo + hi);        // = exp(s - m_hat)
                l[u] += w;
                ull wp = pack2(w, w);
                acc[u][0] = fma2(wp, v0, acc[u][0]);
                acc[u][1] = fma2(wp, v1, acc[u][1]);
                acc[u][2] = fma2(wp, v2, acc[u][2]);
                acc[u][3] = fma2(wp, v3, acc[u][3]);
            }
        }
    }

    #pragma unroll
    for (int u = 0; u < 4; u++) if (val[u]) {
        int qi = qb + u;
        atomicAdd(&g_L[qi * 4 + h], l[u]);
        #pragma unroll
        for (int p = 0; p < 4; p++) {
            float lo, hi; unpack2(acc[u][p], lo, hi);
            atomicAdd(&g_ACCA[(qi * 4 + h) * 8 + p * 2],     lo);
            atomicAdd(&g_ACCA[(qi * 4 + h) * 8 + p * 2 + 1], hi);
        }
    }
}

// ---------------------------------------------------------------------------
// K8: sum over present queries of (ACC/L) -> g_accum[32]; set g_Np. grid 8.
// ---------------------------------------------------------------------------
__global__ void mean_kernel() {
    __shared__ float sw[8][32];
    int tid = threadIdx.x;
    int np = g_cnt;
    float vec[32];
    #pragma unroll
    for (int d = 0; d < 32; d++) vec[d] = 0.f;
    for (int q = blockIdx.x * 256 + tid; q < np; q += 2048) {
        #pragma unroll
        for (int h = 0; h < 4; h++) {
            float invl = 1.f / g_L[q * 4 + h];
            #pragma unroll
            for (int d = 0; d < 8; d++)
                vec[h * 8 + d] = fmaf(g_ACCA[(q * 4 + h) * 8 + d], invl, vec[h * 8 + d]);
        }
    }
    int lane = tid & 31, w = tid >> 5;
    #pragma unroll
    for (int d = 0; d < 32; d++) {
        float r = vec[d];
        for (int o = 16; o; o >>= 1) r += __shfl_xor_sync(0xffffffffu, r, o);
        if (lane == 0) sw[w][d] = r;
    }
    __syncthreads();
    if (tid < 32) {
        float s = 0.f;
        #pragma unroll
        for (int ww = 0; ww < 8; ww++) s += sw[ww][tid];
        atomicAdd(&g_accum[tid], s);
    }
    if (blockIdx.x == 0 && tid == 0) g_Np = (float)np;
}

// ---------------------------------------------------------------------------
// K9: sketch segment merge + out-proj + ctx MLP + irfft + fusion MLP + tanh
// ---------------------------------------------------------------------------
__global__ void final_kernel(const float* __restrict__ aow, const float* __restrict__ aob,
                             const float* __restrict__ cw1, const float* __restrict__ cb1,
                             const float* __restrict__ cw2, const float* __restrict__ cb2,
                             const float* __restrict__ fw1, const float* __restrict__ fb1,
                             const float* __restrict__ fw2, const float* __restrict__ fb2,
                             float* __restrict__ out) {
    __shared__ float m[32], gm[32], c1[16], comb[128], f1[128];
    __shared__ float2 sT3[NBINS];
    int tid = threadIdx.x;
    if (tid < NBINS) {                      // ordered merge of 8 sketch segments
        Tup acc = g_spart[tid * 8];
        #pragma unroll
        for (int s = 1; s < 8; s++) acc = tmerge(acc, g_spart[tid * 8 + s]);
        sT3[tid] = acc.scba;
    }
    float invNp = 1.f / g_Np;
    if (tid < 32) m[tid] = g_accum[tid] * invNp;
    __syncthreads();
    if (tid < 32) {
        float a = aob[tid];
        for (int j = 0; j < 32; j++) a = fmaf(m[j], aow[tid * 32 + j], a);
        gm[tid] = a;
    }
    __syncthreads();
    if (tid < 16) {
        float a = cb1[tid];
        for (int j = 0; j < 32; j++) a = fmaf(gm[j], cw1[tid * 32 + j], a);
        c1[tid] = fmaxf(a, 0.f);
    }
    __syncthreads();
    if (tid < 64) {
        float a = cb2[tid];
        for (int j = 0; j < 16; j++) a = fmaf(c1[j], cw2[tid * 16 + j], a);
        comb[64 + tid] = a;
        float2 T0 = sT3[0], T32 = sT3[32];
        float x = T0.x + ((tid & 1) ? -T32.x : T32.x);
        for (int k = 1; k < 32; k++) {
            float2 Tk = sT3[k];
            float ang = PI2F * (float)(k * tid) / (float)DSZ;
            float sn, cs; sincosf(ang, &sn, &cs);
            x += 2.f * (Tk.x * cs - Tk.y * sn);
        }
        comb[tid] = x * (1.f / (float)DSZ);
    }
    __syncthreads();
    if (tid < 128) {
        float a = fb1[tid];
        for (int j = 0; j < 128; j++) a = fmaf(comb[j], fw1[tid * 128 + j], a);
        f1[tid] = fmaxf(a, 0.f);
    }
    __syncthreads();
    if (tid < 64) {
        float a = fb2[tid];
        for (int j = 0; j < 128; j++) a = fmaf(f1[j], fw2[tid * 128 + j], a);
        out[tid] = tanhf(a);
    }
}

// ---------------------------------------------------------------------------
// launch
// ---------------------------------------------------------------------------
extern "C" void kernel_launch(void* const* d_in, const int* in_sizes, int n_in,
                              void* d_out, int out_size) {
    const int*   seq         = (const int*)  d_in[0];
    const float* hash_logits = (const float*)d_in[1];
    const float* sign_logits = (const float*)d_in[2];
    const float* kmer_emb    = (const float*)d_in[3];
    const float* gc1_w       = (const float*)d_in[4];
    const float* gc1_b       = (const float*)d_in[5];
    const float* gc2_w       = (const float*)d_in[6];
    const float* gc2_b       = (const float*)d_in[7];
    const float* attn_in_w   = (const float*)d_in[8];
    const float* attn_in_b   = (const float*)d_in[9];
    const float* attn_out_w  = (const float*)d_in[10];
    const float* attn_out_b  = (const float*)d_in[11];
    const float* ctx_w1      = (const float*)d_in[12];
    const float* ctx_b1      = (const float*)d_in[13];
    const float* ctx_w2      = (const float*)d_in[14];
    const float* ctx_b2      = (const float*)d_in[15];
    const float* fus_w1      = (const float*)d_in[16];
    const float* fus_b1      = (const float*)d_in[17];
    const float* fus_w2      = (const float*)d_in[18];
    const float* fus_b2      = (const float*)d_in[19];
    float* out = (float*)d_out;

    zero_kernel<<<512, 256>>>();
    scatter_kernel<<<32, 256>>>(seq);
    sketch_kernel<<<dim3(NBINS, 8), 256>>>(seq, hash_logits, sign_logits);
    h1_kernel<<<32, 128>>>(kmer_emb, gc1_w, gc1_b);
    h2_kernel<<<32, 128>>>(gc2_w, gc2_b);
    xqkv_kernel<<<32, 128>>>(attn_in_w, attn_in_b);
    compact_kernel<<<16, 256>>>();
    sumexp_kernel<<<dim3(4, 4, KSPLIT), 256>>>();
    mean_kernel<<<8, 256>>>();
    final_kernel<<<1, 128>>>(attn_out_w, attn_out_b, ctx_w1, ctx_b1, ctx_w2, ctx_b2,
                             fus_w1, fus_b1, fus_w2, fus_b2, out);
}

// round 5
// speedup vs baseline: 1.9447x; 1.1063x over previous
#include <cuda_runtime.h>
#include <math.h>

// ---------------------------------------------------------------------------
// Problem constants
// ---------------------------------------------------------------------------
#define LSEQ   8192
#define KNODES 4096
#define ESZ    32
#define DSZ    64
#define NBINS  33          // D/2+1 rFFT bins
#define PI2F   6.283185307179586f
#define KSPLIT 18

typedef unsigned long long ull;

// ---------------------------------------------------------------------------
// Device scratch (no allocations allowed)
// ---------------------------------------------------------------------------
struct Tup { float2 sa, sb, sc, sba, scb, scba; };

__device__ __align__(16) Tup    g_spart[NBINS * 8];      // sketch segment partials
__device__ __align__(16) float  g_present[KNODES];
__device__ __align__(16) float  g_h1[KNODES * ESZ];
__device__ __align__(16) float  g_h2[KNODES * ESZ];
__device__ __align__(16) float  g_qkv[KNODES * 96];
__device__ __align__(16) float  g_Qc[KNODES * 32];       // compacted, pre-scaled
__device__ __align__(16) float  g_Kc[KNODES * 32];
__device__ __align__(16) float  g_Vc[KNODES * 32];
__device__ int   g_knmax[4];                             // bits of max ||k_h||^2 per head
__device__ float g_L[KNODES * 4];                        // softmax denominators
__device__ __align__(16) float g_ACCA[KNODES * 4 * 8];   // softmax numerators
__device__ __align__(16) float g_accum[ESZ];
__device__ int   g_cnt;
__device__ float g_Np;

// ---------------------------------------------------------------------------
// helpers
// ---------------------------------------------------------------------------
__device__ __forceinline__ float2 cadd(float2 a, float2 b) { return make_float2(a.x + b.x, a.y + b.y); }
__device__ __forceinline__ float2 cmul(float2 a, float2 b) {
    return make_float2(a.x * b.x - a.y * b.y, a.x * b.y + a.y * b.x);
}
__device__ __forceinline__ float2 cfma(float2 a, float2 b, float2 c) {
    c.x = fmaf(a.x, b.x, fmaf(-a.y, b.y, c.x));
    c.y = fmaf(a.x, b.y, fmaf(a.y, b.x, c.y));
    return c;
}
__device__ __forceinline__ Tup tmerge(Tup X, Tup Y) {   // X = earlier segment
    Tup R;
    R.scba = cadd(cadd(X.scba, Y.scba), cadd(cmul(X.sa, Y.scb), cmul(X.sba, Y.sc)));
    R.scb  = cadd(cadd(X.scb,  Y.scb),  cmul(X.sb, Y.sc));
    R.sba  = cadd(cadd(X.sba,  Y.sba),  cmul(X.sa, Y.sb));
    R.sa = cadd(X.sa, Y.sa); R.sb = cadd(X.sb, Y.sb); R.sc = cadd(X.sc, Y.sc);
    return R;
}
// packed f32x2 (Blackwell)
__device__ __forceinline__ ull pack2(float lo, float hi) {
    ull r; asm("mov.b64 %0, {%1, %2};" : "=l"(r) : "f"(lo), "f"(hi)); return r;
}
__device__ __forceinline__ void unpack2(ull v, float& lo, float& hi) {
    asm("mov.b64 {%0, %1}, %2;" : "=f"(lo), "=f"(hi) : "l"(v));
}
__device__ __forceinline__ ull fma2(ull a, ull b, ull c) {
    ull d; asm("fma.rn.f32x2 %0, %1, %2, %3;" : "=l"(d) : "l"(a), "l"(b), "l"(c)); return d;
}

// ---------------------------------------------------------------------------
// K0: zero/init scratch (every replay)
// ---------------------------------------------------------------------------
__global__ void zero_kernel() {
    int i = blockIdx.x * blockDim.x + threadIdx.x;
    if (i < KNODES)        g_present[i] = 0.f;
    if (i < KNODES * 4)    g_L[i] = 0.f;
    if (i < KNODES * 32)   g_ACCA[i] = 0.f;
    if (i < ESZ)           g_accum[i] = 0.f;
    if (i < 4)             g_knmax[i] = 0;
    if (i == 0)            g_cnt = 0;
}

// ---------------------------------------------------------------------------
// K1: k-mer presence scatter
// ---------------------------------------------------------------------------
__global__ void scatter_kernel(const int* __restrict__ seq) {
    int t = blockIdx.x * blockDim.x + threadIdx.x;
    if (t < LSEQ - 5) {
        int id = ((((seq[t] * 4 + seq[t + 1]) * 4 + seq[t + 2]) * 4 + seq[t + 3]) * 4
                  + seq[t + 4]) * 4 + seq[t + 5];
        g_present[id] = 1.f;
    }
}

// ---------------------------------------------------------------------------
// K2: tensor-sketch triple-sum, segment-parallel: grid (33 bins, 8 segments).
// ---------------------------------------------------------------------------
__global__ void sketch_kernel(const int* __restrict__ seq,
                              const float* __restrict__ hash_logits,
                              const float* __restrict__ sign_logits) {
    int bin = blockIdx.x, seg = blockIdx.y;
    int tid = threadIdx.x;
    __shared__ float hs[12][DSZ];
    __shared__ float sgs[12];
    __shared__ float2 cA[4], cB[4], cC[4];
    __shared__ Tup tp[256];

    if (tid < 12) {
        const float* row = hash_logits + tid * DSZ;
        float mx = row[0];
        for (int d = 1; d < DSZ; d++) mx = fmaxf(mx, row[d]);
        float s = 0.f;
        for (int d = 0; d < DSZ; d++) { float e = expf(row[d] - mx); hs[tid][d] = e; s += e; }
        float inv = 1.f / s;
        for (int d = 0; d < DSZ; d++) hs[tid][d] *= inv;
        sgs[tid] = tanhf(sign_logits[tid]);
    }
    __syncthreads();
    if (tid < 192) {                       // 12 rows x 16 lanes, 4 DFT terms each
        int row = tid >> 4, l16 = tid & 15;
        float re = 0.f, im = 0.f;
        #pragma unroll
        for (int t = 0; t < 4; t++) {
            int d = l16 * 4 + t;
            float ang = -PI2F * (float)(bin * d) / (float)DSZ;
            float sn, cs; sincosf(ang, &sn, &cs);
            re = fmaf(hs[row][d], cs, re);
            im = fmaf(hs[row][d], sn, im);
        }
        #pragma unroll
        for (int o = 8; o; o >>= 1) {
            re += __shfl_down_sync(0xffffffffu, re, o, 16);
            im += __shfl_down_sync(0xffffffffu, im, o, 16);
        }
        if (l16 == 0) {
            float f = sgs[row] * (1.f / (float)LSEQ);
            float2 v = make_float2(re * f, im * f);
            int p = row >> 2, c = row & 3;
            if (p == 0) cA[c] = v; else if (p == 1) cB[c] = v; else cC[c] = v;
        }
    }
    __syncthreads();

    float2 sa = {0,0}, sb = {0,0}, sc = {0,0}, sba = {0,0}, scb = {0,0}, scba = {0,0};
    int t0 = seg * 1024 + tid * 4;
    #pragma unroll
    for (int i = 0; i < 4; i++) {
        int ch = seq[t0 + i];
        float2 a = cA[ch], b = cB[ch], c = cC[ch];
        scba = cfma(c, sba, scba);
        scb  = cfma(c, sb,  scb);
        sba  = cfma(b, sa,  sba);
        sa = cadd(sa, a); sb = cadd(sb, b); sc = cadd(sc, c);
    }
    Tup me; me.sa = sa; me.sb = sb; me.sc = sc; me.sba = sba; me.scb = scb; me.scba = scba;
    tp[tid] = me;
    __syncthreads();
    for (int s = 128; s > 0; s >>= 1) {
        if (tid < s) tp[tid] = tmerge(tp[tid], tp[tid + s]);
        __syncthreads();
    }
    if (tid == 0) g_spart[bin * 8 + seg] = tp[0];
}

// ---------------------------------------------------------------------------
// K3: h1 = relu(kmer_emb @ gc1_w^T + b). Block = 32 nodes, 256 threads,
// one thread per (node, out) x4. Coalesced loads, broadcast/conflict-free smem.
// ---------------------------------------------------------------------------
__global__ void h1_kernel(const float* __restrict__ emb,
                          const float* __restrict__ w,
                          const float* __restrict__ b) {
    __shared__ float wt[ESZ][ESZ];       // wt[j][e] = w[e*32+j]
    __shared__ float bs[ESZ];
    __shared__ float xs[32][ESZ + 1];
    int tid = threadIdx.x;
    int base = blockIdx.x * 32;
    for (int idx = tid; idx < 1024; idx += 256) {
        int e = idx >> 5, j = idx & 31;
        wt[j][e] = w[idx];
    }
    if (tid < ESZ) bs[tid] = b[tid];
    for (int idx = tid; idx < 1024; idx += 256) {
        xs[idx >> 5][idx & 31] = emb[base * 32 + idx];
    }
    __syncthreads();
    #pragma unroll
    for (int it = 0; it < 4; it++) {
        int idx = tid + it * 256;
        int n = idx >> 5, e = idx & 31;
        float acc = bs[e];
        #pragma unroll
        for (int j = 0; j < ESZ; j++) acc = fmaf(xs[n][j], wt[j][e], acc);
        g_h1[base * 32 + idx] = fmaxf(acc, 0.f);
    }
}

// ---------------------------------------------------------------------------
// K4: h2 = relu((nadj@h1) @ gc2_w^T + b). Same tiling; neighbor lists built
// once per node, aggregation one element per thread (coalesced on h1 rows).
// ---------------------------------------------------------------------------
__global__ void h2_kernel(const float* __restrict__ w, const float* __restrict__ b) {
    __shared__ float wt[ESZ][ESZ];
    __shared__ float bs[ESZ];
    __shared__ float ag[32][ESZ + 1];
    __shared__ int   nb[32][4];
    __shared__ float nrm[32];
    int tid = threadIdx.x;
    int base = blockIdx.x * 32;
    for (int idx = tid; idx < 1024; idx += 256) {
        int e = idx >> 5, j = idx & 31;
        wt[j][e] = w[idx];
    }
    if (tid < ESZ) bs[tid] = b[tid];
    if (tid < 32) {
        int i = base + tid;
        bool pres = g_present[i] > 0.f;
        int bse = (i & 1023) * 4;
        float cnt = 0.f;
        #pragma unroll
        for (int r = 0; r < 4; r++) {
            int j = bse + r;
            bool ok = pres && (j != i) && (g_present[j] > 0.f);
            nb[tid][r] = ok ? j : -1;
            cnt += ok ? 1.f : 0.f;
        }
        nrm[tid] = pres ? 1.f / (cnt + 1e-6f) : 0.f;
    }
    __syncthreads();
    #pragma unroll
    for (int it = 0; it < 4; it++) {
        int idx = tid + it * 256;
        int n = idx >> 5, e = idx & 31;
        float a = 0.f;
        #pragma unroll
        for (int r = 0; r < 4; r++) {
            int j = nb[n][r];
            if (j >= 0) a += g_h1[j * 32 + e];
        }
        ag[n][e] = a * nrm[n];
    }
    __syncthreads();
    #pragma unroll
    for (int it = 0; it < 4; it++) {
        int idx = tid + it * 256;
        int n = idx >> 5, e = idx & 31;
        float acc = bs[e];
        #pragma unroll
        for (int j = 0; j < ESZ; j++) acc = fmaf(ag[n][j], wt[j][e], acc);
        g_h2[base * 32 + idx] = fmaxf(acc, 0.f);
    }
}

// ---------------------------------------------------------------------------
// K5: x = nadj@h2 ; qkv = x @ attn_in_w^T + attn_in_b. Same tiling, 96 outs.
// ---------------------------------------------------------------------------
__global__ void xqkv_kernel(const float* __restrict__ w, const float* __restrict__ b) {
    __shared__ float wt[ESZ][96];        // wt[j][o] = w[o*32+j]
    __shared__ float bs[96];
    __shared__ float ag[32][ESZ + 1];
    __shared__ int   nb[32][4];
    __shared__ float nrm[32];
    int tid = threadIdx.x;
    int base = blockIdx.x * 32;
    for (int idx = tid; idx < 96 * ESZ; idx += 256) {
        int o = idx >> 5, j = idx & 31;
        wt[j][o] = w[idx];
    }
    if (tid < 96) bs[tid] = b[tid];
    if (tid < 32) {
        int i = base + tid;
        bool pres = g_present[i] > 0.f;
        int bse = (i & 1023) * 4;
        float cnt = 0.f;
        #pragma unroll
        for (int r = 0; r < 4; r++) {
            int j = bse + r;
            bool ok = pres && (j != i) && (g_present[j] > 0.f);
            nb[tid][r] = ok ? j : -1;
            cnt += ok ? 1.f : 0.f;
        }
        nrm[tid] = pres ? 1.f / (cnt + 1e-6f) : 0.f;
    }
    __syncthreads();
    #pragma unroll
    for (int it = 0; it < 4; it++) {
        int idx = tid + it * 256;
        int n = idx >> 5, e = idx & 31;
        float a = 0.f;
        #pragma unroll
        for (int r = 0; r < 4; r++) {
            int j = nb[n][r];
            if (j >= 0) a += g_h2[j * 32 + e];
        }
        ag[n][e] = a * nrm[n];
    }
    __syncthreads();
    #pragma unroll
    for (int it = 0; it < 12; it++) {
        int idx = tid + it * 256;            // idx = n*96 + o
        int n = idx / 96, o = idx - n * 96;
        float acc = bs[o];
        #pragma unroll
        for (int j = 0; j < ESZ; j++) acc = fmaf(ag[n][j], wt[j][o], acc);
        g_qkv[base * 96 + idx] = acc;
    }
}

// ---------------------------------------------------------------------------
// K6: compact present nodes; also max ||k||^2 per head.
// ---------------------------------------------------------------------------
__global__ void compact_kernel() {
    int i = blockIdx.x * blockDim.x + threadIdx.x;
    if (i >= KNODES) return;
    if (g_present[i] > 0.f) {
        int p = atomicAdd(&g_cnt, 1);
        const float scale = 0.35355339059327373f;  // 1/sqrt(8)
        const float4* src = (const float4*)&g_qkv[i * 96];
        float4* q4 = (float4*)&g_Qc[p * 32];
        float4* k4 = (float4*)&g_Kc[p * 32];
        float4* v4 = (float4*)&g_Vc[p * 32];
        #pragma unroll
        for (int j = 0; j < 8; j++) {
            float4 q = src[j];
            q.x *= scale; q.y *= scale; q.z *= scale; q.w *= scale;
            q4[j] = q;
            k4[j] = src[8 + j];
            v4[j] = src[16 + j];
        }
        #pragma unroll
        for (int h = 0; h < 4; h++) {
            float4 a = src[8 + 2 * h], b = src[8 + 2 * h + 1];
            float ksq = a.x*a.x + a.y*a.y + a.z*a.z + a.w*a.w
                      + b.x*b.x + b.y*b.y + b.z*b.z + b.w*b.w;
            atomicMax(&g_knmax[h], __float_as_int(ksq));   // ksq >= 0: bit-compare ok
        }
    }
}

// ---------------------------------------------------------------------------
// K7: single-pass softmax numerator/denominator with upper-bound shift.
// m_hat = ||q||*max||k|| >= true max (Cauchy-Schwarz); shift cancels in ACC/L.
// ---------------------------------------------------------------------------
__global__ void __launch_bounds__(256, 2) sumexp_kernel() {
    __shared__ ull ks2[128 * 4];
    __shared__ ull vs2[128 * 4];
    int h = blockIdx.y, z = blockIdx.z;
    int tid = threadIdx.x;
    int np = g_cnt;
    float knorm = sqrtf(__int_as_float(g_knmax[h]));
    int qb = blockIdx.x * 1024 + tid * 4;

    ull qp[4][4], c0[4], acc[4][4];
    float l[4];
    bool val[4];
    #pragma unroll
    for (int u = 0; u < 4; u++) {
        int qi = qb + u;
        val[u] = qi < np;
        float qv[8];
        #pragma unroll
        for (int d = 0; d < 8; d++) qv[d] = 0.f;
        if (val[u]) {
            float4 x0 = *(const float4*)&g_Qc[qi * 32 + h * 8];
            float4 x1 = *(const float4*)&g_Qc[qi * 32 + h * 8 + 4];
            qv[0]=x0.x; qv[1]=x0.y; qv[2]=x0.z; qv[3]=x0.w;
            qv[4]=x1.x; qv[5]=x1.y; qv[6]=x1.z; qv[7]=x1.w;
        }
        float qsq = 0.f;
        #pragma unroll
        for (int d = 0; d < 8; d++) qsq = fmaf(qv[d], qv[d], qsq);
        float mh = fminf(sqrtf(qsq) * knorm, 80.f);
        #pragma unroll
        for (int p = 0; p < 4; p++) qp[u][p] = pack2(qv[2*p], qv[2*p+1]);
        c0[u] = pack2(-mh, 0.f);
        l[u] = 0.f;
        #pragma unroll
        for (int p = 0; p < 4; p++) acc[u][p] = pack2(0.f, 0.f);
    }

    int kper = (np + KSPLIT - 1) / KSPLIT;
    int kbeg = z * kper, kend = min(np, kbeg + kper);
    for (int kt = kbeg; kt < kend; kt += 128) {
        int jn = min(128, kend - kt);
        __syncthreads();
        #pragma unroll
        for (int it = 0; it < 2; it++) {
            int idx = tid + it * 256;
            int j = idx >> 2, p = idx & 3;
            if (j < jn) {
                ks2[idx] = *(const ull*)&g_Kc[(kt + j) * 32 + h * 8 + p * 2];
                vs2[idx] = *(const ull*)&g_Vc[(kt + j) * 32 + h * 8 + p * 2];
            }
        }
        __syncthreads();
        #pragma unroll 2
        for (int j = 0; j < jn; j++) {
            ull k0 = ks2[j*4], k1 = ks2[j*4+1], k2 = ks2[j*4+2], k3 = ks2[j*4+3];
            ull v0 = vs2[j*4], v1 = vs2[j*4+1], v2 = vs2[j*4+2], v3 = vs2[j*4+3];
            #pragma unroll
            for (int u = 0; u < 4; u++) {
                ull sp = fma2(qp[u][0], k0,
                         fma2(qp[u][1], k1,
                         fma2(qp[u][2], k2,
                         fma2(qp[u][3], k3, c0[u]))));
                float lo, hi; unpack2(sp, lo, hi);
                float w = __expf(lo + hi);        // = exp(s - m_hat)
                l[u] += w;
                ull wp = pack2(w, w);
                acc[u][0] = fma2(wp, v0, acc[u][0]);
                acc[u][1] = fma2(wp, v1, acc[u][1]);
                acc[u][2] = fma2(wp, v2, acc[u][2]);
                acc[u][3] = fma2(wp, v3, acc[u][3]);
            }
        }
    }

    #pragma unroll
    for (int u = 0; u < 4; u++) if (val[u]) {
        int qi = qb + u;
        atomicAdd(&g_L[qi * 4 + h], l[u]);
        #pragma unroll
        for (int p = 0; p < 4; p++) {
            float lo, hi; unpack2(acc[u][p], lo, hi);
            atomicAdd(&g_ACCA[(qi * 4 + h) * 8 + p * 2],     lo);
            atomicAdd(&g_ACCA[(qi * 4 + h) * 8 + p * 2 + 1], hi);
        }
    }
}

// ---------------------------------------------------------------------------
// K8: sum over present queries of (ACC/L) -> g_accum[32]; set g_Np. grid 8.
// ---------------------------------------------------------------------------
__global__ void mean_kernel() {
    __shared__ float sw[8][32];
    int tid = threadIdx.x;
    int np = g_cnt;
    float vec[32];
    #pragma unroll
    for (int d = 0; d < 32; d++) vec[d] = 0.f;
    for (int q = blockIdx.x * 256 + tid; q < np; q += 2048) {
        #pragma unroll
        for (int h = 0; h < 4; h++) {
            float invl = 1.f / g_L[q * 4 + h];
            #pragma unroll
            for (int d = 0; d < 8; d++)
                vec[h * 8 + d] = fmaf(g_ACCA[(q * 4 + h) * 8 + d], invl, vec[h * 8 + d]);
        }
    }
    int lane = tid & 31, w = tid >> 5;
    #pragma unroll
    for (int d = 0; d < 32; d++) {
        float r = vec[d];
        for (int o = 16; o; o >>= 1) r += __shfl_xor_sync(0xffffffffu, r, o);
        if (lane == 0) sw[w][d] = r;
    }
    __syncthreads();
    if (tid < 32) {
        float s = 0.f;
        #pragma unroll
        for (int ww = 0; ww < 8; ww++) s += sw[ww][tid];
        atomicAdd(&g_accum[tid], s);
    }
    if (blockIdx.x == 0 && tid == 0) g_Np = (float)np;
}

// ---------------------------------------------------------------------------
// K9: sketch segment merge + out-proj + ctx MLP + irfft + fusion MLP + tanh
// ---------------------------------------------------------------------------
__global__ void final_kernel(const float* __restrict__ aow, const float* __restrict__ aob,
                             const float* __restrict__ cw1, const float* __restrict__ cb1,
                             const float* __restrict__ cw2, const float* __restrict__ cb2,
                             const float* __restrict__ fw1, const float* __restrict__ fb1,
                             const float* __restrict__ fw2, const float* __restrict__ fb2,
                             float* __restrict__ out) {
    __shared__ float m[32], gm[32], c1[16], comb[128], f1[128];
    __shared__ float2 sT3[NBINS];
    int tid = threadIdx.x;
    if (tid < NBINS) {                      // ordered merge of 8 sketch segments
        Tup acc = g_spart[tid * 8];
        #pragma unroll
        for (int s = 1; s < 8; s++) acc = tmerge(acc, g_spart[tid * 8 + s]);
        sT3[tid] = acc.scba;
    }
    float invNp = 1.f / g_Np;
    if (tid < 32) m[tid] = g_accum[tid] * invNp;
    __syncthreads();
    if (tid < 32) {
        float a = aob[tid];
        for (int j = 0; j < 32; j++) a = fmaf(m[j], aow[tid * 32 + j], a);
        gm[tid] = a;
    }
    __syncthreads();
    if (tid < 16) {
        float a = cb1[tid];
        for (int j = 0; j < 32; j++) a = fmaf(gm[j], cw1[tid * 32 + j], a);
        c1[tid] = fmaxf(a, 0.f);
    }
    __syncthreads();
    if (tid < 64) {
        float a = cb2[tid];
        for (int j = 0; j < 16; j++) a = fmaf(c1[j], cw2[tid * 16 + j], a);
        comb[64 + tid] = a;
        float2 T0 = sT3[0], T32 = sT3[32];
        float x = T0.x + ((tid & 1) ? -T32.x : T32.x);
        for (int k = 1; k < 32; k++) {
            float2 Tk = sT3[k];
            float ang = PI2F * (float)(k * tid) / (float)DSZ;
            float sn, cs; sincosf(ang, &sn, &cs);
            x += 2.f * (Tk.x * cs - Tk.y * sn);
        }
        comb[tid] = x * (1.f / (float)DSZ);
    }
    __syncthreads();
    if (tid < 128) {
        float a = fb1[tid];
        for (int j = 0; j < 128; j++) a = fmaf(comb[j], fw1[tid * 128 + j], a);
        f1[tid] = fmaxf(a, 0.f);
    }
    __syncthreads();
    if (tid < 64) {
        float a = fb2[tid];
        for (int j = 0; j < 128; j++) a = fmaf(f1[j], fw2[tid * 128 + j], a);
        out[tid] = tanhf(a);
    }
}

// ---------------------------------------------------------------------------
// launch
// ---------------------------------------------------------------------------
extern "C" void kernel_launch(void* const* d_in, const int* in_sizes, int n_in,
                              void* d_out, int out_size) {
    const int*   seq         = (const int*)  d_in[0];
    const float* hash_logits = (const float*)d_in[1];
    const float* sign_logits = (const float*)d_in[2];
    const float* kmer_emb    = (const float*)d_in[3];
    const float* gc1_w       = (const float*)d_in[4];
    const float* gc1_b       = (const float*)d_in[5];
    const float* gc2_w       = (const float*)d_in[6];
    const float* gc2_b       = (const float*)d_in[7];
    const float* attn_in_w   = (const float*)d_in[8];
    const float* attn_in_b   = (const float*)d_in[9];
    const float* attn_out_w  = (const float*)d_in[10];
    const float* attn_out_b  = (const float*)d_in[11];
    const float* ctx_w1      = (const float*)d_in[12];
    const float* ctx_b1      = (const float*)d_in[13];
    const float* ctx_w2      = (const float*)d_in[14];
    const float* ctx_b2      = (const float*)d_in[15];
    const float* fus_w1      = (const float*)d_in[16];
    const float* fus_b1      = (const float*)d_in[17];
    const float* fus_w2      = (const float*)d_in[18];
    const float* fus_b2      = (const float*)d_in[19];
    float* out = (float*)d_out;

    zero_kernel<<<512, 256>>>();
    scatter_kernel<<<32, 256>>>(seq);
    sketch_kernel<<<dim3(NBINS, 8), 256>>>(seq, hash_logits, sign_logits);
    h1_kernel<<<128, 256>>>(kmer_emb, gc1_w, gc1_b);
    h2_kernel<<<128, 256>>>(gc2_w, gc2_b);
    xqkv_kernel<<<128, 256>>>(attn_in_w, attn_in_b);
    compact_kernel<<<16, 256>>>();
    sumexp_kernel<<<dim3(4, 4, KSPLIT), 256>>>();
    mean_kernel<<<8, 256>>>();
    final_kernel<<<1, 128>>>(attn_out_w, attn_out_b, ctx_w1, ctx_b1, ctx_w2, ctx_b2,
                             fus_w1, fus_b1, fus_w2, fus_b2, out);
}

// round 7
// speedup vs baseline: 1.9745x; 1.0153x over previous
#include <cuda_runtime.h>
#include <math.h>

// ---------------------------------------------------------------------------
// Problem constants
// ---------------------------------------------------------------------------
#define LSEQ   8192
#define KNODES 4096
#define ESZ    32
#define DSZ    64
#define NBINS  33          // D/2+1 rFFT bins
#define PI2F   6.283185307179586f
#define NB     148         // one block per SM: co-residency unconditionally guaranteed
#define KSPLIT 9           // sumexp tasks = 4 qtiles * 4 heads * 9 = 144 <= NB

typedef unsigned long long ull;

// ---------------------------------------------------------------------------
// Device scratch (no allocations allowed)
// ---------------------------------------------------------------------------
struct Tup { float2 sa, sb, sc, sba, scb, scba; };

__device__ __align__(16) Tup   g_spart[NBINS * 8];
__device__ __align__(16) float g_present[KNODES];
__device__ __align__(16) float g_h1[KNODES * ESZ];
__device__ __align__(16) float g_h2[KNODES * ESZ];
__device__ __align__(16) float g_Qc[KNODES * 32];
__device__ __align__(16) float g_Kc[KNODES * 32];
__device__ __align__(16) float g_Vc[KNODES * 32];
__device__ int   g_knmax[4];
__device__ __align__(16) float g_L[KNODES * 4];
__device__ __align__(16) float g_ACCA[KNODES * 32];
__device__ __align__(16) float g_accum[ESZ];
__device__ int   g_cnt;
__device__ int   g_bar_cnt;     // grid barrier arrive counter (returns to 0 each barrier)
__device__ int   g_bar_gen;     // grid barrier generation (monotonic across replays)

// ---------------------------------------------------------------------------
// helpers
// ---------------------------------------------------------------------------
__device__ __forceinline__ float2 cadd(float2 a, float2 b) { return make_float2(a.x + b.x, a.y + b.y); }
__device__ __forceinline__ float2 cmul(float2 a, float2 b) {
    return make_float2(a.x * b.x - a.y * b.y, a.x * b.y + a.y * b.x);
}
__device__ __forceinline__ float2 cfma(float2 a, float2 b, float2 c) {
    c.x = fmaf(a.x, b.x, fmaf(-a.y, b.y, c.x));
    c.y = fmaf(a.x, b.y, fmaf(a.y, b.x, c.y));
    return c;
}
__device__ __forceinline__ Tup tmerge(Tup X, Tup Y) {   // X = earlier segment
    Tup R;
    R.scba = cadd(cadd(X.scba, Y.scba), cadd(cmul(X.sa, Y.scb), cmul(X.sba, Y.sc)));
    R.scb  = cadd(cadd(X.scb,  Y.scb),  cmul(X.sb, Y.sc));
    R.sba  = cadd(cadd(X.sba,  Y.sba),  cmul(X.sa, Y.sb));
    R.sa = cadd(X.sa, Y.sa); R.sb = cadd(X.sb, Y.sb); R.sc = cadd(X.sc, Y.sc);
    return R;
}
__device__ __forceinline__ ull pack2(float lo, float hi) {
    ull r; asm("mov.b64 %0, {%1, %2};" : "=l"(r) : "f"(lo), "f"(hi)); return r;
}
__device__ __forceinline__ void unpack2(ull v, float& lo, float& hi) {
    asm("mov.b64 {%0, %1}, %2;" : "=f"(lo), "=f"(hi) : "l"(v));
}
__device__ __forceinline__ ull fma2(ull a, ull b, ull c) {
    ull d; asm("fma.rn.f32x2 %0, %1, %2, %3;" : "=l"(d) : "l"(a), "l"(b), "l"(c)); return d;
}

// ---- grid-wide barrier (generation-based; all NB blocks participate) ----
__device__ __forceinline__ int ld_acq(int* p) {
    int v; asm volatile("ld.acquire.gpu.b32 %0, [%1];" : "=r"(v) : "l"(p) : "memory"); return v;
}
__device__ __forceinline__ void st_rel(int* p, int v) {
    asm volatile("st.release.gpu.b32 [%0], %1;" :: "l"(p), "r"(v) : "memory");
}
__device__ __forceinline__ void gsync() {
    __threadfence();                     // publish this thread's writes
    __syncthreads();
    if (threadIdx.x == 0) {
        int gen = ld_acq(&g_bar_gen);
        int t = atomicAdd(&g_bar_cnt, 1);
        if (t == NB - 1) {
            atomicExch(&g_bar_cnt, 0);   // all arrived; none touch cnt until gen bump
            st_rel(&g_bar_gen, gen + 1);
        } else {
            while (ld_acq(&g_bar_gen) == gen) { __nanosleep(32); }
        }
    }
    __syncthreads();
    __threadfence();                     // gpu-scope: post-barrier loads see fresh data
}

// ---------------------------------------------------------------------------
// phase-union shared memory (~30KB; 1 block/SM always fits)
// ---------------------------------------------------------------------------
struct SkS {
    float hs[12][DSZ];
    float sgs[12];
    float2 cA[4], cB[4], cC[4];
    Tup tp[256];
};
struct H1S { float wt[32][32]; float bs[32]; float xs[32][33]; };
struct H2S { float wt[32][32]; float bs[32]; float ag[32][33]; int nb[32][4]; float nrm[32]; };
struct XqS { float wt[32][96]; float bs[96]; float ag[32][33]; int nb[32][4]; float nrm[32];
             float qs[32][96]; int slot[32]; };
struct SeS { ull ks2[512]; ull vs2[512]; };
struct MfS { float m[32], gm[32], c1[16], comb[128], f1[128]; float2 sT3[NBINS]; float sw[8][32]; };
union Smem { SkS sk; H1S h1; H2S h2; XqS xq; SeS se; MfS mf; };

// ---------------------------------------------------------------------------
// THE megakernel (persistent, 148 blocks, 6 grid barriers)
// ---------------------------------------------------------------------------
__global__ void __launch_bounds__(256) mega_kernel(
    const int* __restrict__ seq,
    const float* __restrict__ hash_logits, const float* __restrict__ sign_logits,
    const float* __restrict__ emb,
    const float* __restrict__ gc1w, const float* __restrict__ gc1b,
    const float* __restrict__ gc2w, const float* __restrict__ gc2b,
    const float* __restrict__ aiw,  const float* __restrict__ aib,
    const float* __restrict__ aow,  const float* __restrict__ aob,
    const float* __restrict__ cw1,  const float* __restrict__ cb1,
    const float* __restrict__ cw2,  const float* __restrict__ cb2,
    const float* __restrict__ fw1,  const float* __restrict__ fb1,
    const float* __restrict__ fw2,  const float* __restrict__ fb2,
    float* __restrict__ out)
{
    __shared__ Smem sm;
    int tid = threadIdx.x, bid = blockIdx.x;
    int gtid = bid * 256 + tid;

    // ===== Phase 1: zero scratch + tensor-sketch (264 tasks) + h1 (128 tiles) =====
    for (int i = gtid; i < KNODES * 32; i += NB * 256) g_ACCA[i] = 0.f;
    for (int i = gtid; i < KNODES * 4;  i += NB * 256) g_L[i] = 0.f;
    for (int i = gtid; i < KNODES;      i += NB * 256) g_present[i] = 0.f;
    if (gtid < ESZ) g_accum[gtid] = 0.f;
    if (gtid < 4)   g_knmax[gtid] = 0;
    if (gtid == 0)  g_cnt = 0;

    for (int task = bid; task < 264; task += NB) {      // sketch: bin = task%33, seg = task/33
        int bin = task % NBINS, seg = task / NBINS;
        __syncthreads();                                // smem reuse across iterations
        if (tid < 12) {
            const float* row = hash_logits + tid * DSZ;
            float mx = row[0];
            for (int d = 1; d < DSZ; d++) mx = fmaxf(mx, row[d]);
            float s = 0.f;
            for (int d = 0; d < DSZ; d++) { float e = expf(row[d] - mx); sm.sk.hs[tid][d] = e; s += e; }
            float inv = 1.f / s;
            for (int d = 0; d < DSZ; d++) sm.sk.hs[tid][d] *= inv;
            sm.sk.sgs[tid] = tanhf(sign_logits[tid]);
        }
        __syncthreads();
        if (tid < 192) {                    // 12 rows x 16 lanes, 4 DFT terms each
            int row = tid >> 4, l16 = tid & 15;
            float re = 0.f, im = 0.f;
            #pragma unroll
            for (int t = 0; t < 4; t++) {
                int d = l16 * 4 + t;
                float ang = -PI2F * (float)(bin * d) / (float)DSZ;
                float sn, cs; sincosf(ang, &sn, &cs);
                re = fmaf(sm.sk.hs[row][d], cs, re);
                im = fmaf(sm.sk.hs[row][d], sn, im);
            }
            #pragma unroll
            for (int o = 8; o; o >>= 1) {
                re += __shfl_down_sync(0xffffffffu, re, o, 16);
                im += __shfl_down_sync(0xffffffffu, im, o, 16);
            }
            if (l16 == 0) {
                float f = sm.sk.sgs[row] * (1.f / (float)LSEQ);
                float2 v = make_float2(re * f, im * f);
                int p = row >> 2, c = row & 3;
                if (p == 0) sm.sk.cA[c] = v; else if (p == 1) sm.sk.cB[c] = v; else sm.sk.cC[c] = v;
            }
        }
        __syncthreads();
        float2 sa = {0,0}, sb = {0,0}, sc = {0,0}, sba = {0,0}, scb = {0,0}, scba = {0,0};
        int t0 = seg * 1024 + tid * 4;
        #pragma unroll
        for (int i = 0; i < 4; i++) {
            int ch = seq[t0 + i];
            float2 a = sm.sk.cA[ch], b = sm.sk.cB[ch], c = sm.sk.cC[ch];
            scba = cfma(c, sba, scba);
            scb  = cfma(c, sb,  scb);
            sba  = cfma(b, sa,  sba);
            sa = cadd(sa, a); sb = cadd(sb, b); sc = cadd(sc, c);
        }
        Tup me; me.sa = sa; me.sb = sb; me.sc = sc; me.sba = sba; me.scb = scb; me.scba = scba;
        sm.sk.tp[tid] = me;
        __syncthreads();
        for (int s = 128; s > 0; s >>= 1) {
            if (tid < s) sm.sk.tp[tid] = tmerge(sm.sk.tp[tid], sm.sk.tp[tid + s]);
            __syncthreads();
        }
        if (tid == 0) g_spart[bin * 8 + seg] = sm.sk.tp[0];
    }
    if (bid < 128) {                        // h1 tile
        int base = bid * 32;
        __syncthreads();                    // smem union handoff (sketch -> h1)
        for (int idx = tid; idx < 1024; idx += 256) {
            int e = idx >> 5, j = idx & 31;
            sm.h1.wt[j][e] = gc1w[idx];
        }
        if (tid < ESZ) sm.h1.bs[tid] = gc1b[tid];
        for (int idx = tid; idx < 1024; idx += 256)
            sm.h1.xs[idx >> 5][idx & 31] = emb[base * 32 + idx];
        __syncthreads();
        #pragma unroll
        for (int it = 0; it < 4; it++) {
            int idx = tid + it * 256;
            int n = idx >> 5, e = idx & 31;
            float acc = sm.h1.bs[e];
            #pragma unroll
            for (int j = 0; j < ESZ; j++) acc = fmaf(sm.h1.xs[n][j], sm.h1.wt[j][e], acc);
            g_h1[base * 32 + idx] = fmaxf(acc, 0.f);
        }
    }
    gsync();

    // ===== Phase 2: k-mer presence scatter =====
    if (gtid < LSEQ - 5) {
        int t = gtid;
        int id = ((((seq[t] * 4 + seq[t + 1]) * 4 + seq[t + 2]) * 4 + seq[t + 3]) * 4
                  + seq[t + 4]) * 4 + seq[t + 5];
        g_present[id] = 1.f;
    }
    gsync();

    // ===== Phase 3: h2 = relu((nadj@h1) @ gc2_w^T + b) =====
    if (bid < 128) {
        int base = bid * 32;
        for (int idx = tid; idx < 1024; idx += 256) {
            int e = idx >> 5, j = idx & 31;
            sm.h2.wt[j][e] = gc2w[idx];
        }
        if (tid < ESZ) sm.h2.bs[tid] = gc2b[tid];
        if (tid < 32) {
            int i = base + tid;
            bool pres = g_present[i] > 0.f;
            int bse = (i & 1023) * 4;
            float cnt = 0.f;
            #pragma unroll
            for (int r = 0; r < 4; r++) {
                int j = bse + r;
                bool ok = pres && (j != i) && (g_present[j] > 0.f);
                sm.h2.nb[tid][r] = ok ? j : -1;
                cnt += ok ? 1.f : 0.f;
            }
            sm.h2.nrm[tid] = pres ? 1.f / (cnt + 1e-6f) : 0.f;
        }
        __syncthreads();
        #pragma unroll
        for (int it = 0; it < 4; it++) {
            int idx = tid + it * 256;
            int n = idx >> 5, e = idx & 31;
            float a = 0.f;
            #pragma unroll
            for (int r = 0; r < 4; r++) {
                int j = sm.h2.nb[n][r];
                if (j >= 0) a += g_h1[j * 32 + e];
            }
            sm.h2.ag[n][e] = a * sm.h2.nrm[n];
        }
        __syncthreads();
        #pragma unroll
        for (int it = 0; it < 4; it++) {
            int idx = tid + it * 256;
            int n = idx >> 5, e = idx & 31;
            float acc = sm.h2.bs[e];
            #pragma unroll
            for (int j = 0; j < ESZ; j++) acc = fmaf(sm.h2.ag[n][j], sm.h2.wt[j][e], acc);
            g_h2[base * 32 + idx] = fmaxf(acc, 0.f);
        }
    }
    gsync();

    // ===== Phase 4: xqkv + fused compact (qkv never touches global) =====
    if (bid < 128) {
        int base = bid * 32;
        for (int idx = tid; idx < 96 * ESZ; idx += 256) {
            int o = idx >> 5, j = idx & 31;
            sm.xq.wt[j][o] = aiw[idx];
        }
        if (tid < 96) sm.xq.bs[tid] = aib[tid];
        if (tid < 32) {
            int i = base + tid;
            bool pres = g_present[i] > 0.f;
            int bse = (i & 1023) * 4;
            float cnt = 0.f;
            #pragma unroll
            for (int r = 0; r < 4; r++) {
                int j = bse + r;
                bool ok = pres && (j != i) && (g_present[j] > 0.f);
                sm.xq.nb[tid][r] = ok ? j : -1;
                cnt += ok ? 1.f : 0.f;
            }
            sm.xq.nrm[tid] = pres ? 1.f / (cnt + 1e-6f) : 0.f;
        }
        __syncthreads();
        #pragma unroll
        for (int it = 0; it < 4; it++) {
            int idx = tid + it * 256;
            int n = idx >> 5, e = idx & 31;
            float a = 0.f;
            #pragma unroll
            for (int r = 0; r < 4; r++) {
                int j = sm.xq.nb[n][r];
                if (j >= 0) a += g_h2[j * 32 + e];
            }
            sm.xq.ag[n][e] = a * sm.xq.nrm[n];
        }
        __syncthreads();
        #pragma unroll
        for (int it = 0; it < 12; it++) {
            int idx = tid + it * 256;            // idx = n*96 + o
            int n = idx / 96, o = idx - n * 96;
            float acc = sm.xq.bs[o];
            #pragma unroll
            for (int j = 0; j < ESZ; j++) acc = fmaf(sm.xq.ag[n][j], sm.xq.wt[j][o], acc);
            sm.xq.qs[n][o] = acc;
        }
        __syncthreads();
        if (tid < 32) {
            int i = base + tid;
            sm.xq.slot[tid] = (g_present[i] > 0.f) ? atomicAdd(&g_cnt, 1) : -1;
        }
        __syncthreads();
        for (int idx = tid; idx < 3072; idx += 256) {
            int n = idx / 96, o = idx - n * 96;
            int p = sm.xq.slot[n];
            if (p >= 0) {
                float v = sm.xq.qs[n][o];
                if (o < 32)      g_Qc[p * 32 + o]        = v * 0.35355339059327373f;
                else if (o < 64) g_Kc[p * 32 + (o - 32)] = v;
                else             g_Vc[p * 32 + (o - 64)] = v;
            }
        }
        if (tid < 128) {
            int n = tid >> 2, h = tid & 3;
            if (sm.xq.slot[n] >= 0) {
                float ksq = 0.f;
                #pragma unroll
                for (int d = 0; d < 8; d++) {
                    float v = sm.xq.qs[n][32 + h * 8 + d];
                    ksq = fmaf(v, v, ksq);
                }
                atomicMax(&g_knmax[h], __float_as_int(ksq));  // ksq >= 0: bit-compare ok
            }
        }
    }
    gsync();

    // ===== Phase 5: single-pass softmax sums (upper-bound shift, f32x2) =====
    if (bid < 4 * 4 * KSPLIT) {              // 144 tasks
        int qt = bid & 3, h = (bid >> 2) & 3, z = bid >> 4;
        int np = g_cnt;
        float knorm = sqrtf(__int_as_float(g_knmax[h]));
        int qb = qt * 1024 + tid * 4;

        ull qp[4][4], c0[4], acc[4][4];
        float l[4];
        bool val[4];
        #pragma unroll
        for (int u = 0; u < 4; u++) {
            int qi = qb + u;
            val[u] = qi < np;
            float qv[8];
            #pragma unroll
            for (int d = 0; d < 8; d++) qv[d] = 0.f;
            if (val[u]) {
                float4 x0 = *(const float4*)&g_Qc[qi * 32 + h * 8];
                float4 x1 = *(const float4*)&g_Qc[qi * 32 + h * 8 + 4];
                qv[0]=x0.x; qv[1]=x0.y; qv[2]=x0.z; qv[3]=x0.w;
                qv[4]=x1.x; qv[5]=x1.y; qv[6]=x1.z; qv[7]=x1.w;
            }
            float qsq = 0.f;
            #pragma unroll
            for (int d = 0; d < 8; d++) qsq = fmaf(qv[d], qv[d], qsq);
            float mh = fminf(sqrtf(qsq) * knorm, 80.f);
            #pragma unroll
            for (int p = 0; p < 4; p++) qp[u][p] = pack2(qv[2*p], qv[2*p+1]);
            c0[u] = pack2(-mh, 0.f);
            l[u] = 0.f;
            #pragma unroll
            for (int p = 0; p < 4; p++) acc[u][p] = pack2(0.f, 0.f);
        }

        int kper = (np + KSPLIT - 1) / KSPLIT;
        int kbeg = z * kper, kend = min(np, kbeg + kper);
        for (int kt = kbeg; kt < kend; kt += 128) {
            int jn = min(128, kend - kt);
            __syncthreads();
            #pragma unroll
            for (int it = 0; it < 2; it++) {
                int idx = tid + it * 256;
                int j = idx >> 2, p = idx & 3;
                if (j < jn) {
                    sm.se.ks2[idx] = *(const ull*)&g_Kc[(kt + j) * 32 + h * 8 + p * 2];
                    sm.se.vs2[idx] = *(const ull*)&g_Vc[(kt + j) * 32 + h * 8 + p * 2];
                }
            }
            __syncthreads();
            #pragma unroll 2
            for (int j = 0; j < jn; j++) {
                ull k0 = sm.se.ks2[j*4], k1 = sm.se.ks2[j*4+1], k2 = sm.se.ks2[j*4+2], k3 = sm.se.ks2[j*4+3];
                ull v0 = sm.se.vs2[j*4], v1 = sm.se.vs2[j*4+1], v2 = sm.se.vs2[j*4+2], v3 = sm.se.vs2[j*4+3];
                #pragma unroll
                for (int u = 0; u < 4; u++) {
                    ull sp = fma2(qp[u][0], k0,
                             fma2(qp[u][1], k1,
                             fma2(qp[u][2], k2,
                             fma2(qp[u][3], k3, c0[u]))));
                    float lo, hi; unpack2(sp, lo, hi);
                    float w = __expf(lo + hi);        // = exp(s - m_hat)
                    l[u] += w;
                    ull wp = pack2(w, w);
                    acc[u][0] = fma2(wp, v0, acc[u][0]);
                    acc[u][1] = fma2(wp, v1, acc[u][1]);
                    acc[u][2] = fma2(wp, v2, acc[u][2]);
                    acc[u][3] = fma2(wp, v3, acc[u][3]);
                }
            }
        }

        #pragma unroll
        for (int u = 0; u < 4; u++) if (val[u]) {
            int qi = qb + u;
            atomicAdd(&g_L[qi * 4 + h], l[u]);
            #pragma unroll
            for (int p = 0; p < 4; p++) {
                float lo, hi; unpack2(acc[u][p], lo, hi);
                atomicAdd(&g_ACCA[(qi * 4 + h) * 8 + p * 2],     lo);
                atomicAdd(&g_ACCA[(qi * 4 + h) * 8 + p * 2 + 1], hi);
            }
        }
    }
    gsync();

    // ===== Phase 6: mean over present queries of ACC/L -> g_accum =====
    {
        int np = g_cnt;
        float vec[32];
        #pragma unroll
        for (int d = 0; d < 32; d++) vec[d] = 0.f;
        int q = gtid;                         // NB*256 = 37888 >= np: one q per thread
        if (q < np) {
            float4 lv = *(const float4*)&g_L[q * 4];
            float invh[4] = {1.f / lv.x, 1.f / lv.y, 1.f / lv.z, 1.f / lv.w};
            #pragma unroll
            for (int h = 0; h < 4; h++) {
                float4 a0 = *(const float4*)&g_ACCA[(q * 4 + h) * 8];
                float4 a1 = *(const float4*)&g_ACCA[(q * 4 + h) * 8 + 4];
                vec[h*8+0] = a0.x * invh[h]; vec[h*8+1] = a0.y * invh[h];
                vec[h*8+2] = a0.z * invh[h]; vec[h*8+3] = a0.w * invh[h];
                vec[h*8+4] = a1.x * invh[h]; vec[h*8+5] = a1.y * invh[h];
                vec[h*8+6] = a1.z * invh[h]; vec[h*8+7] = a1.w * invh[h];
            }
        }
        int lane = tid & 31, w = tid >> 5;
        #pragma unroll
        for (int d = 0; d < 32; d++) {
            float r = vec[d];
            for (int o = 16; o; o >>= 1) r += __shfl_xor_sync(0xffffffffu, r, o);
            if (lane == 0) sm.mf.sw[w][d] = r;
        }
        __syncthreads();
        if (tid < 32) {
            float s = 0.f;
            #pragma unroll
            for (int ww = 0; ww < 8; ww++) s += sm.mf.sw[ww][tid];
            if (s != 0.f) atomicAdd(&g_accum[tid], s);
        }
    }
    gsync();

    // ===== Phase 7 (block 0): sketch merge + out-proj + ctx + irfft + fusion =====
    if (bid == 0) {
        if (tid < NBINS) {                  // ordered merge of 8 sketch segments
            Tup acc = g_spart[tid * 8];
            #pragma unroll
            for (int s = 1; s < 8; s++) acc = tmerge(acc, g_spart[tid * 8 + s]);
            sm.mf.sT3[tid] = acc.scba;
        }
        float invNp = 1.f / (float)g_cnt;
        if (tid < 32) sm.mf.m[tid] = g_accum[tid] * invNp;
        __syncthreads();
        if (tid < 32) {
            float a = aob[tid];
            for (int j = 0; j < 32; j++) a = fmaf(sm.mf.m[j], aow[tid * 32 + j], a);
            sm.mf.gm[tid] = a;
        }
        __syncthreads();
        if (tid < 16) {
            float a = cb1[tid];
            for (int j = 0; j < 32; j++) a = fmaf(sm.mf.gm[j], cw1[tid * 32 + j], a);
            sm.mf.c1[tid] = fmaxf(a, 0.f);
        }
        __syncthreads();
        if (tid < 64) {
            float a = cb2[tid];
            for (int j = 0; j < 16; j++) a = fmaf(sm.mf.c1[j], cw2[tid * 16 + j], a);
            sm.mf.comb[64 + tid] = a;
            float2 T0 = sm.mf.sT3[0], T32 = sm.mf.sT3[32];
            float x = T0.x + ((tid & 1) ? -T32.x : T32.x);
            for (int k = 1; k < 32; k++) {
                float2 Tk = sm.mf.sT3[k];
                float ang = PI2F * (float)(k * tid) / (float)DSZ;
                float sn, cs; sincosf(ang, &sn, &cs);
                x += 2.f * (Tk.x * cs - Tk.y * sn);
            }
            sm.mf.comb[tid] = x * (1.f / (float)DSZ);
        }
        __syncthreads();
        if (tid < 128) {
            float a = fb1[tid];
            for (int j = 0; j < 128; j++) a = fmaf(sm.mf.comb[j], fw1[tid * 128 + j], a);
            sm.mf.f1[tid] = fmaxf(a, 0.f);
        }
        __syncthreads();
        if (tid < 64) {
            float a = fb2[tid];
            for (int j = 0; j < 128; j++) a = fmaf(sm.mf.f1[j], fw2[tid * 128 + j], a);
            out[tid] = tanhf(a);
        }
    }
}

// ---------------------------------------------------------------------------
// launch: ONE persistent kernel, 148 blocks (1/SM — barrier-safe)
// ---------------------------------------------------------------------------
extern "C" void kernel_launch(void* const* d_in, const int* in_sizes, int n_in,
                              void* d_out, int out_size) {
    const int*   seq         = (const int*)  d_in[0];
    const float* hash_logits = (const float*)d_in[1];
    const float* sign_logits = (const float*)d_in[2];
    const float* kmer_emb    = (const float*)d_in[3];
    const float* gc1_w       = (const float*)d_in[4];
    const float* gc1_b       = (const float*)d_in[5];
    const float* gc2_w       = (const float*)d_in[6];
    const float* gc2_b       = (const float*)d_in[7];
    const float* attn_in_w   = (const float*)d_in[8];
    const float* attn_in_b   = (const float*)d_in[9];
    const float* attn_out_w  = (const float*)d_in[10];
    const float* attn_out_b  = (const float*)d_in[11];
    const float* ctx_w1      = (const float*)d_in[12];
    const float* ctx_b1      = (const float*)d_in[13];
    const float* ctx_w2      = (const float*)d_in[14];
    const float* ctx_b2      = (const float*)d_in[15];
    const float* fus_w1      = (const float*)d_in[16];
    const float* fus_b1      = (const float*)d_in[17];
    const float* fus_w2      = (const float*)d_in[18];
    const float* fus_b2      = (const float*)d_in[19];
    float* out = (float*)d_out;

    mega_kernel<<<NB, 256>>>(seq, hash_logits, sign_logits, kmer_emb,
                             gc1_w, gc1_b, gc2_w, gc2_b,
                             attn_in_w, attn_in_b, attn_out_w, attn_out_b,
                             ctx_w1, ctx_b1, ctx_w2, ctx_b2,
                             fus_w1, fus_b1, fus_w2, fus_b2, out);
}